// round 1
// baseline (speedup 1.0000x reference)
#include <cuda_runtime.h>
#include <cuda_bf16.h>
#include <stdint.h>

#define BB   4
#define DIM  64
#define CDIM 128
#define DD   64
#define HH   64
#define WW   64
#define NSP  (DD*HH*WW)   /* 262144 spatial positions per batch */
#define HW   (HH*WW)      /* 4096 */

// bf16 scratch for q, k, v in [b][channel][d*HW + h*W + w] layout (same as x)
__device__ __nv_bfloat16 g_q[(size_t)BB * DIM * NSP];
__device__ __nv_bfloat16 g_k[(size_t)BB * DIM * NSP];
__device__ __nv_bfloat16 g_v[(size_t)BB * DIM * NSP];

__device__ __forceinline__ uint32_t ldpair(const __nv_bfloat16* p) {
    return *reinterpret_cast<const uint32_t*>(p);
}

__device__ __forceinline__ void mma16816(float c[4], const uint32_t a[4],
                                         uint32_t b0, uint32_t b1) {
    asm volatile(
        "mma.sync.aligned.m16n8k16.row.col.f32.bf16.bf16.f32 "
        "{%0,%1,%2,%3}, {%4,%5,%6,%7}, {%8,%9}, {%0,%1,%2,%3};\n"
        : "+f"(c[0]), "+f"(c[1]), "+f"(c[2]), "+f"(c[3])
        : "r"(a[0]), "r"(a[1]), "r"(a[2]), "r"(a[3]), "r"(b0), "r"(b1));
}

// ---------------------------------------------------------------------------
// Pass 1a: Q = Wq[64x64] * X[64 x NSP] + bq   (per batch), output bf16
// CTA: M=64 (all out ch), N=256 voxels, K=64. 8 warps = 2(m) x 4(n).
// ---------------------------------------------------------------------------
__global__ void __launch_bounds__(256) conv_q_kernel(
    const float* __restrict__ x, const float* __restrict__ wq,
    const float* __restrict__ bq)
{
    __shared__ __nv_bfloat16 Ws[64 * 72];    // [m][k] pitch 72
    __shared__ __nv_bfloat16 Xs[256 * 72];   // [n][k] pitch 72
    __shared__ float bs[64];

    const int tid = threadIdx.x;
    const int b  = blockIdx.y;
    const int n0 = blockIdx.x * 256;
    const float* xb = x + (size_t)b * DIM * NSP;

    for (int i = tid; i < 64 * 64; i += 256)
        Ws[(i >> 6) * 72 + (i & 63)] = __float2bfloat16(wq[i]);
    if (tid < 64) bs[tid] = bq[tid];
    #pragma unroll
    for (int c = 0; c < 64; ++c)
        Xs[tid * 72 + c] = __float2bfloat16(xb[(size_t)c * NSP + n0 + tid]);
    __syncthreads();

    const int warp = tid >> 5, lane = tid & 31;
    const int mw = warp & 1, nw = warp >> 1;
    const int lr = lane >> 2, lc = lane & 3;

    float acc[2][8][4];
    #pragma unroll
    for (int mi = 0; mi < 2; ++mi)
        #pragma unroll
        for (int nf = 0; nf < 8; ++nf)
            #pragma unroll
            for (int e = 0; e < 4; ++e) acc[mi][nf][e] = 0.f;

    #pragma unroll
    for (int kc = 0; kc < 4; ++kc) {
        const int k0 = kc * 16 + lc * 2;
        uint32_t a[2][4];
        #pragma unroll
        for (int mi = 0; mi < 2; ++mi) {
            const int m = mw * 32 + mi * 16 + lr;
            a[mi][0] = ldpair(&Ws[m * 72 + k0]);
            a[mi][1] = ldpair(&Ws[(m + 8) * 72 + k0]);
            a[mi][2] = ldpair(&Ws[m * 72 + k0 + 8]);
            a[mi][3] = ldpair(&Ws[(m + 8) * 72 + k0 + 8]);
        }
        #pragma unroll
        for (int nf = 0; nf < 8; ++nf) {
            const int n = nw * 64 + nf * 8 + lr;
            uint32_t b0 = ldpair(&Xs[n * 72 + k0]);
            uint32_t b1 = ldpair(&Xs[n * 72 + k0 + 8]);
            mma16816(acc[0][nf], a[0], b0, b1);
            mma16816(acc[1][nf], a[1], b0, b1);
        }
    }

    __nv_bfloat16* qb = g_q + (size_t)b * DIM * NSP;
    #pragma unroll
    for (int mi = 0; mi < 2; ++mi) {
        const int m = mw * 32 + mi * 16 + lr;
        const float bi0 = bs[m], bi1 = bs[m + 8];
        #pragma unroll
        for (int nf = 0; nf < 8; ++nf) {
            const int n = nw * 64 + nf * 8 + lc * 2;
            __nv_bfloat162 p0 = __floats2bfloat162_rn(acc[mi][nf][0] + bi0,
                                                      acc[mi][nf][1] + bi0);
            __nv_bfloat162 p1 = __floats2bfloat162_rn(acc[mi][nf][2] + bi1,
                                                      acc[mi][nf][3] + bi1);
            *reinterpret_cast<__nv_bfloat162*>(&qb[(size_t)m * NSP + n0 + n]) = p0;
            *reinterpret_cast<__nv_bfloat162*>(&qb[(size_t)(m + 8) * NSP + n0 + n]) = p1;
        }
    }
}

// ---------------------------------------------------------------------------
// Pass 1b: [K;V] = [Wk;Wv][128x128] * CTX[128 x NSP] + [bk;bv]  (ctx read once)
// CTA: M=128 (64 k-ch + 64 v-ch), N=128 voxels, K=128. 8 warps = 4(m) x 2(n).
// Dynamic smem: Ws 128x136 + Xs 128x136 bf16 + 128 f32 bias.
// ---------------------------------------------------------------------------
#define KV_SMEM_BYTES (2 * 128 * 136 * (int)sizeof(__nv_bfloat16) + 128 * (int)sizeof(float))

__global__ void __launch_bounds__(256) conv_kv_kernel(
    const float* __restrict__ ctx,
    const float* __restrict__ wk, const float* __restrict__ bk,
    const float* __restrict__ wv, const float* __restrict__ bv)
{
    extern __shared__ __nv_bfloat16 sm[];
    __nv_bfloat16* Ws = sm;                 // [m=128][k pitch 136]
    __nv_bfloat16* Xs = sm + 128 * 136;     // [n=128][k pitch 136]
    float* bs = reinterpret_cast<float*>(sm + 2 * 128 * 136);

    const int tid = threadIdx.x;
    const int b  = blockIdx.y;
    const int n0 = blockIdx.x * 128;
    const float* cb = ctx + (size_t)b * CDIM * NSP;

    for (int i = tid; i < 128 * 128; i += 256) {
        int o = i >> 7, c = i & 127;
        float w = (o < 64) ? wk[o * 128 + c] : wv[(o - 64) * 128 + c];
        Ws[o * 136 + c] = __float2bfloat16(w);
    }
    if (tid < 128) bs[tid] = (tid < 64) ? bk[tid] : bv[tid - 64];
    for (int i = tid; i < 128 * 128; i += 256) {
        int c = i >> 7, n = i & 127;
        Xs[n * 136 + c] = __float2bfloat16(cb[(size_t)c * NSP + n0 + n]);
    }
    __syncthreads();

    const int warp = tid >> 5, lane = tid & 31;
    const int mw = warp & 3, nw = warp >> 2;
    const int lr = lane >> 2, lc = lane & 3;

    float acc[2][8][4];
    #pragma unroll
    for (int mi = 0; mi < 2; ++mi)
        #pragma unroll
        for (int nf = 0; nf < 8; ++nf)
            #pragma unroll
            for (int e = 0; e < 4; ++e) acc[mi][nf][e] = 0.f;

    #pragma unroll
    for (int kc = 0; kc < 8; ++kc) {
        const int k0 = kc * 16 + lc * 2;
        uint32_t a[2][4];
        #pragma unroll
        for (int mi = 0; mi < 2; ++mi) {
            const int m = mw * 32 + mi * 16 + lr;
            a[mi][0] = ldpair(&Ws[m * 136 + k0]);
            a[mi][1] = ldpair(&Ws[(m + 8) * 136 + k0]);
            a[mi][2] = ldpair(&Ws[m * 136 + k0 + 8]);
            a[mi][3] = ldpair(&Ws[(m + 8) * 136 + k0 + 8]);
        }
        #pragma unroll
        for (int nf = 0; nf < 8; ++nf) {
            const int n = nw * 64 + nf * 8 + lr;
            uint32_t b0 = ldpair(&Xs[n * 136 + k0]);
            uint32_t b1 = ldpair(&Xs[n * 136 + k0 + 8]);
            mma16816(acc[0][nf], a[0], b0, b1);
            mma16816(acc[1][nf], a[1], b0, b1);
        }
    }

    __nv_bfloat16* kb = g_k + (size_t)b * DIM * NSP;
    __nv_bfloat16* vb = g_v + (size_t)b * DIM * NSP;
    #pragma unroll
    for (int mi = 0; mi < 2; ++mi) {
        const int m = mw * 32 + mi * 16 + lr;
        const float bi0 = bs[m], bi1 = bs[m + 8];
        __nv_bfloat16* r0 = (m < 64) ? (kb + (size_t)m * NSP) : (vb + (size_t)(m - 64) * NSP);
        __nv_bfloat16* r1 = (m + 8 < 64) ? (kb + (size_t)(m + 8) * NSP) : (vb + (size_t)(m + 8 - 64) * NSP);
        #pragma unroll
        for (int nf = 0; nf < 8; ++nf) {
            const int n = nw * 64 + nf * 8 + lc * 2;
            __nv_bfloat162 p0 = __floats2bfloat162_rn(acc[mi][nf][0] + bi0,
                                                      acc[mi][nf][1] + bi0);
            __nv_bfloat162 p1 = __floats2bfloat162_rn(acc[mi][nf][2] + bi1,
                                                      acc[mi][nf][3] + bi1);
            *reinterpret_cast<__nv_bfloat162*>(&r0[n0 + n]) = p0;
            *reinterpret_cast<__nv_bfloat162*>(&r1[n0 + n]) = p1;
        }
    }
}

// ---------------------------------------------------------------------------
// Pass 2: per-(b,c,d) attention. 1 CTA = 128 threads (4 warps), 64x64 problem.
// S = 0.125 * Q K^T (mma), fp32 softmax over g, O = P V (mma) + x residual.
// ---------------------------------------------------------------------------
__global__ void __launch_bounds__(128) attn_kernel(
    const float* __restrict__ x, float* __restrict__ out)
{
    __shared__ __nv_bfloat16 Qs[64 * 72];   // Q, later reused to hold P (bf16)
    __shared__ __nv_bfloat16 Ks[64 * 72];   // K [g][w]
    __shared__ __nv_bfloat16 Vt[64 * 72];   // V transposed: [w][g]
    __shared__ float Ss[64 * 66];           // logits / exp

    const int tid = threadIdx.x;
    const int d = blockIdx.x, c = blockIdx.y, b = blockIdx.z;
    const size_t base = (((size_t)b * DIM + c) * DD + d) * HW;

    const uint32_t* qsrc = reinterpret_cast<const uint32_t*>(g_q + base);
    const uint32_t* ksrc = reinterpret_cast<const uint32_t*>(g_k + base);
    const uint32_t* vsrc = reinterpret_cast<const uint32_t*>(g_v + base);

    for (int i = tid; i < 2048; i += 128) {
        const int h = i >> 5, wp = i & 31;
        *reinterpret_cast<uint32_t*>(&Qs[h * 72 + wp * 2]) = qsrc[i];
        *reinterpret_cast<uint32_t*>(&Ks[h * 72 + wp * 2]) = ksrc[i];
        uint32_t vv = vsrc[i];
        __nv_bfloat162 v2 = *reinterpret_cast<__nv_bfloat162*>(&vv);
        Vt[(wp * 2) * 72 + h]     = v2.x;
        Vt[(wp * 2 + 1) * 72 + h] = v2.y;
    }
    __syncthreads();

    const int warp = tid >> 5, lane = tid & 31;
    const int lr = lane >> 2, lc = lane & 3;

    // ---- S = Q K^T * scale ----
    {
        float acc[8][4];
        #pragma unroll
        for (int nf = 0; nf < 8; ++nf)
            #pragma unroll
            for (int e = 0; e < 4; ++e) acc[nf][e] = 0.f;

        #pragma unroll
        for (int kc = 0; kc < 4; ++kc) {
            const int k0 = kc * 16 + lc * 2;
            const int m = warp * 16 + lr;
            uint32_t a[4];
            a[0] = ldpair(&Qs[m * 72 + k0]);
            a[1] = ldpair(&Qs[(m + 8) * 72 + k0]);
            a[2] = ldpair(&Qs[m * 72 + k0 + 8]);
            a[3] = ldpair(&Qs[(m + 8) * 72 + k0 + 8]);
            #pragma unroll
            for (int nf = 0; nf < 8; ++nf) {
                const int n = nf * 8 + lr;
                uint32_t b0 = ldpair(&Ks[n * 72 + k0]);
                uint32_t b1 = ldpair(&Ks[n * 72 + k0 + 8]);
                mma16816(acc[nf], a, b0, b1);
            }
        }
        const float sc = 0.125f;  // DIM^-0.5
        const int m = warp * 16 + lr;
        #pragma unroll
        for (int nf = 0; nf < 8; ++nf) {
            const int n = nf * 8 + lc * 2;
            Ss[m * 66 + n]           = acc[nf][0] * sc;
            Ss[m * 66 + n + 1]       = acc[nf][1] * sc;
            Ss[(m + 8) * 66 + n]     = acc[nf][2] * sc;
            Ss[(m + 8) * 66 + n + 1] = acc[nf][3] * sc;
        }
    }
    __syncthreads();

    // ---- softmax over g (2 threads per row), write P as bf16 into Qs ----
    {
        const int row = tid >> 1, part = tid & 1;
        const float* srow = &Ss[row * 66 + part * 32];
        float v[32];
        float mx = -1e30f;
        #pragma unroll
        for (int j = 0; j < 32; ++j) { v[j] = srow[j]; mx = fmaxf(mx, v[j]); }
        mx = fmaxf(mx, __shfl_xor_sync(0xffffffffu, mx, 1));
        float s = 0.f;
        #pragma unroll
        for (int j = 0; j < 32; ++j) { v[j] = __expf(v[j] - mx); s += v[j]; }
        s += __shfl_xor_sync(0xffffffffu, s, 1);
        const float inv = 1.0f / s;
        uint32_t* prow = reinterpret_cast<uint32_t*>(&Qs[row * 72 + part * 32]);
        #pragma unroll
        for (int j = 0; j < 16; ++j) {
            __nv_bfloat162 p2 = __floats2bfloat162_rn(v[2 * j] * inv, v[2 * j + 1] * inv);
            prow[j] = *reinterpret_cast<uint32_t*>(&p2);
        }
    }
    __syncthreads();

    // ---- O = P V + x ----
    {
        float acc[8][4];
        #pragma unroll
        for (int nf = 0; nf < 8; ++nf)
            #pragma unroll
            for (int e = 0; e < 4; ++e) acc[nf][e] = 0.f;

        #pragma unroll
        for (int kc = 0; kc < 4; ++kc) {
            const int k0 = kc * 16 + lc * 2;
            const int m = warp * 16 + lr;
            uint32_t a[4];
            a[0] = ldpair(&Qs[m * 72 + k0]);        // P
            a[1] = ldpair(&Qs[(m + 8) * 72 + k0]);
            a[2] = ldpair(&Qs[m * 72 + k0 + 8]);
            a[3] = ldpair(&Qs[(m + 8) * 72 + k0 + 8]);
            #pragma unroll
            for (int nf = 0; nf < 8; ++nf) {
                const int n = nf * 8 + lr;
                uint32_t b0 = ldpair(&Vt[n * 72 + k0]);
                uint32_t b1 = ldpair(&Vt[n * 72 + k0 + 8]);
                mma16816(acc[nf], a, b0, b1);
            }
        }
        const float* xb = x + base;
        float* ob = out + base;
        const int m = warp * 16 + lr;
        #pragma unroll
        for (int nf = 0; nf < 8; ++nf) {
            const int n = nf * 8 + lc * 2;
            float2 xr0 = *reinterpret_cast<const float2*>(&xb[m * 64 + n]);
            float2 xr1 = *reinterpret_cast<const float2*>(&xb[(m + 8) * 64 + n]);
            float2 o0 = make_float2(acc[nf][0] + xr0.x, acc[nf][1] + xr0.y);
            float2 o1 = make_float2(acc[nf][2] + xr1.x, acc[nf][3] + xr1.y);
            *reinterpret_cast<float2*>(&ob[m * 64 + n]) = o0;
            *reinterpret_cast<float2*>(&ob[(m + 8) * 64 + n]) = o1;
        }
    }
}

// ---------------------------------------------------------------------------
extern "C" void kernel_launch(void* const* d_in, const int* in_sizes, int n_in,
                              void* d_out, int out_size)
{
    const float* x   = (const float*)d_in[0];
    const float* ctx = (const float*)d_in[1];
    const float* wq  = (const float*)d_in[2];
    const float* bq  = (const float*)d_in[3];
    const float* wk  = (const float*)d_in[4];
    const float* bk  = (const float*)d_in[5];
    const float* wv  = (const float*)d_in[6];
    const float* bv  = (const float*)d_in[7];
    float* out = (float*)d_out;

    conv_q_kernel<<<dim3(NSP / 256, BB), 256>>>(x, wq, bq);

    cudaFuncSetAttribute(conv_kv_kernel,
                         cudaFuncAttributeMaxDynamicSharedMemorySize,
                         KV_SMEM_BYTES);
    conv_kv_kernel<<<dim3(NSP / 128, BB), 256, KV_SMEM_BYTES>>>(ctx, wk, bk, wv, bv);

    attn_kernel<<<dim3(DD, DIM, BB), 128>>>(x, out);
}

// round 2
// speedup vs baseline: 1.5166x; 1.5166x over previous
#include <cuda_runtime.h>
#include <cuda_bf16.h>
#include <stdint.h>

#define BB   4
#define DIM  64
#define CDIM 128
#define DD   64
#define HH   64
#define WW   64
#define NSP  (DD*HH*WW)   /* 262144 spatial positions per batch */
#define HW   (HH*WW)      /* 4096 */

// bf16 scratch for q, k, v in [b][channel][d*HW + h*W + w] layout (same as x)
__device__ __nv_bfloat16 g_q[(size_t)BB * DIM * NSP];
__device__ __nv_bfloat16 g_k[(size_t)BB * DIM * NSP];
__device__ __nv_bfloat16 g_v[(size_t)BB * DIM * NSP];

__device__ __forceinline__ uint32_t ldpair(const __nv_bfloat16* p) {
    return *reinterpret_cast<const uint32_t*>(p);
}

__device__ __forceinline__ void mma16816(float c[4], const uint32_t a[4],
                                         uint32_t b0, uint32_t b1) {
    asm volatile(
        "mma.sync.aligned.m16n8k16.row.col.f32.bf16.bf16.f32 "
        "{%0,%1,%2,%3}, {%4,%5,%6,%7}, {%8,%9}, {%0,%1,%2,%3};\n"
        : "+f"(c[0]), "+f"(c[1]), "+f"(c[2]), "+f"(c[3])
        : "r"(a[0]), "r"(a[1]), "r"(a[2]), "r"(a[3]), "r"(b0), "r"(b1));
}

__device__ __forceinline__ uint32_t packbf(float a, float b) {
    __nv_bfloat162 p = __floats2bfloat162_rn(a, b);
    return *reinterpret_cast<uint32_t*>(&p);
}

// ---------------------------------------------------------------------------
// Pass 1a: Q = Wq[64x64] * X[64 x NSP] + bq   (per batch), output bf16
// CTA: 256 thr. M=64, N=128, K=64. 8 warps = 4(m) x 2(n), warp tile 16x64.
// acc = 32 regs/thread -> ~4 CTAs/SM by regs.
// ---------------------------------------------------------------------------
__global__ void __launch_bounds__(256) conv_q_kernel(
    const float* __restrict__ x, const float* __restrict__ wq,
    const float* __restrict__ bq)
{
    __shared__ __nv_bfloat16 Ws[64 * 72];    // [m][k] pitch 72
    __shared__ __nv_bfloat16 Xs[128 * 72];   // [n][k] pitch 72
    __shared__ float bs[64];

    const int tid = threadIdx.x;
    const int b  = blockIdx.y;
    const int n0 = blockIdx.x * 128;
    const float* xb = x + (size_t)b * DIM * NSP;

    for (int i = tid; i < 64 * 64; i += 256)
        Ws[(i >> 6) * 72 + (i & 63)] = __float2bfloat16(wq[i]);
    if (tid < 64) bs[tid] = bq[tid];
    #pragma unroll
    for (int i = tid; i < 128 * 64; i += 256) {
        const int c = i >> 7, n = i & 127;
        Xs[n * 72 + c] = __float2bfloat16(xb[(size_t)c * NSP + n0 + n]);
    }
    __syncthreads();

    const int warp = tid >> 5, lane = tid & 31;
    const int mw = warp >> 1, nw = warp & 1;
    const int lr = lane >> 2, lc = lane & 3;
    const int m = mw * 16 + lr;

    float acc[8][4];
    #pragma unroll
    for (int nf = 0; nf < 8; ++nf)
        #pragma unroll
        for (int e = 0; e < 4; ++e) acc[nf][e] = 0.f;

    #pragma unroll
    for (int kc = 0; kc < 4; ++kc) {
        const int k0 = kc * 16 + lc * 2;
        uint32_t a[4];
        a[0] = ldpair(&Ws[m * 72 + k0]);
        a[1] = ldpair(&Ws[(m + 8) * 72 + k0]);
        a[2] = ldpair(&Ws[m * 72 + k0 + 8]);
        a[3] = ldpair(&Ws[(m + 8) * 72 + k0 + 8]);
        #pragma unroll
        for (int nf = 0; nf < 8; ++nf) {
            const int n = nw * 64 + nf * 8 + lr;
            uint32_t b0 = ldpair(&Xs[n * 72 + k0]);
            uint32_t b1 = ldpair(&Xs[n * 72 + k0 + 8]);
            mma16816(acc[nf], a, b0, b1);
        }
    }

    __nv_bfloat16* qb = g_q + (size_t)b * DIM * NSP;
    const float bi0 = bs[m], bi1 = bs[m + 8];
    #pragma unroll
    for (int nf = 0; nf < 8; ++nf) {
        const int n = nw * 64 + nf * 8 + lc * 2;
        *reinterpret_cast<uint32_t*>(&qb[(size_t)m * NSP + n0 + n]) =
            packbf(acc[nf][0] + bi0, acc[nf][1] + bi0);
        *reinterpret_cast<uint32_t*>(&qb[(size_t)(m + 8) * NSP + n0 + n]) =
            packbf(acc[nf][2] + bi1, acc[nf][3] + bi1);
    }
}

// ---------------------------------------------------------------------------
// Pass 1b: [K;V] = [Wk;Wv][128x128] * CTX[128 x NSP] + [bk;bv]  (ctx read once)
// CTA: 512 thr, M=128, weights loaded once, inner loop over 4 N-tiles of 128.
// 16 warps = 4(m) x 4(n), warp tile 32x32, acc[2][4][4] = 32 regs.
// ---------------------------------------------------------------------------
#define KV_TILES 4
#define KV_SMEM_BYTES (2 * 128 * 136 * (int)sizeof(__nv_bfloat16) + 128 * (int)sizeof(float))

__global__ void __launch_bounds__(512) conv_kv_kernel(
    const float* __restrict__ ctx,
    const float* __restrict__ wk, const float* __restrict__ bk,
    const float* __restrict__ wv, const float* __restrict__ bv)
{
    extern __shared__ __nv_bfloat16 sm[];
    __nv_bfloat16* Ws = sm;                 // [m=128][k pitch 136]
    __nv_bfloat16* Xs = sm + 128 * 136;     // [n=128][k pitch 136]
    float* bs = reinterpret_cast<float*>(sm + 2 * 128 * 136);

    const int tid = threadIdx.x;
    const int b = blockIdx.y;
    const float* cb = ctx + (size_t)b * CDIM * NSP;

    for (int i = tid; i < 128 * 128; i += 512) {
        int o = i >> 7, c = i & 127;
        float w = (o < 64) ? wk[o * 128 + c] : wv[(o - 64) * 128 + c];
        Ws[o * 136 + c] = __float2bfloat16(w);
    }
    if (tid < 128) bs[tid] = (tid < 64) ? bk[tid] : bv[tid - 64];

    const int warp = tid >> 5, lane = tid & 31;
    const int mw = warp & 3, nw = warp >> 2;
    const int lr = lane >> 2, lc = lane & 3;

    __nv_bfloat16* kb = g_k + (size_t)b * DIM * NSP;
    __nv_bfloat16* vb = g_v + (size_t)b * DIM * NSP;

    for (int t = 0; t < KV_TILES; ++t) {
        const int n0 = blockIdx.x * (KV_TILES * 128) + t * 128;
        #pragma unroll
        for (int i = tid; i < 128 * 128; i += 512) {
            int c = i >> 7, n = i & 127;
            Xs[n * 136 + c] = __float2bfloat16(cb[(size_t)c * NSP + n0 + n]);
        }
        __syncthreads();

        float acc[2][4][4];
        #pragma unroll
        for (int mi = 0; mi < 2; ++mi)
            #pragma unroll
            for (int nf = 0; nf < 4; ++nf)
                #pragma unroll
                for (int e = 0; e < 4; ++e) acc[mi][nf][e] = 0.f;

        #pragma unroll
        for (int kc = 0; kc < 8; ++kc) {
            const int k0 = kc * 16 + lc * 2;
            uint32_t a[2][4];
            #pragma unroll
            for (int mi = 0; mi < 2; ++mi) {
                const int m = mw * 32 + mi * 16 + lr;
                a[mi][0] = ldpair(&Ws[m * 136 + k0]);
                a[mi][1] = ldpair(&Ws[(m + 8) * 136 + k0]);
                a[mi][2] = ldpair(&Ws[m * 136 + k0 + 8]);
                a[mi][3] = ldpair(&Ws[(m + 8) * 136 + k0 + 8]);
            }
            #pragma unroll
            for (int nf = 0; nf < 4; ++nf) {
                const int n = nw * 32 + nf * 8 + lr;
                uint32_t b0 = ldpair(&Xs[n * 136 + k0]);
                uint32_t b1 = ldpair(&Xs[n * 136 + k0 + 8]);
                mma16816(acc[0][nf], a[0], b0, b1);
                mma16816(acc[1][nf], a[1], b0, b1);
            }
        }

        #pragma unroll
        for (int mi = 0; mi < 2; ++mi) {
            const int m = mw * 32 + mi * 16 + lr;
            const float bi0 = bs[m], bi1 = bs[m + 8];
            __nv_bfloat16* r0 = (m < 64) ? (kb + (size_t)m * NSP)
                                         : (vb + (size_t)(m - 64) * NSP);
            __nv_bfloat16* r1 = (m + 8 < 64) ? (kb + (size_t)(m + 8) * NSP)
                                             : (vb + (size_t)(m + 8 - 64) * NSP);
            #pragma unroll
            for (int nf = 0; nf < 4; ++nf) {
                const int n = nw * 32 + nf * 8 + lc * 2;
                *reinterpret_cast<uint32_t*>(&r0[n0 + n]) =
                    packbf(acc[mi][nf][0] + bi0, acc[mi][nf][1] + bi0);
                *reinterpret_cast<uint32_t*>(&r1[n0 + n]) =
                    packbf(acc[mi][nf][2] + bi1, acc[mi][nf][3] + bi1);
            }
        }
        __syncthreads();
    }
}

// ---------------------------------------------------------------------------
// Pass 2: per-(b,c,d) attention. 1 CTA = 128 threads (4 warps), 64x64 problem.
// S = Q K^T (mma) -> REGISTER softmax (quad shuffles) -> P frags in regs ->
// O = P V (mma) + x residual. Single __syncthreads, no S/P smem round-trip.
// ---------------------------------------------------------------------------
__global__ void __launch_bounds__(128) attn_kernel(
    const float* __restrict__ x, float* __restrict__ out)
{
    __shared__ __nv_bfloat16 Qs[64 * 72];   // Q [h][w]
    __shared__ __nv_bfloat16 Ks[64 * 72];   // K [g][w]
    __shared__ __nv_bfloat16 Vt[64 * 72];   // V transposed: [w][g]

    const int tid = threadIdx.x;
    const int d = blockIdx.x, c = blockIdx.y, b = blockIdx.z;
    const size_t base = (((size_t)b * DIM + c) * DD + d) * HW;

    const uint32_t* qsrc = reinterpret_cast<const uint32_t*>(g_q + base);
    const uint32_t* ksrc = reinterpret_cast<const uint32_t*>(g_k + base);
    const uint32_t* vsrc = reinterpret_cast<const uint32_t*>(g_v + base);

    #pragma unroll
    for (int i = tid; i < 2048; i += 128) {
        const int h = i >> 5, wp = i & 31;
        *reinterpret_cast<uint32_t*>(&Qs[h * 72 + wp * 2]) = qsrc[i];
        *reinterpret_cast<uint32_t*>(&Ks[h * 72 + wp * 2]) = ksrc[i];
        uint32_t vv = vsrc[i];
        __nv_bfloat162 v2 = *reinterpret_cast<__nv_bfloat162*>(&vv);
        Vt[(wp * 2) * 72 + h]     = v2.x;
        Vt[(wp * 2 + 1) * 72 + h] = v2.y;
    }
    __syncthreads();

    const int warp = tid >> 5, lane = tid & 31;
    const int lr = lane >> 2, lc = lane & 3;
    const int m = warp * 16 + lr;

    // ---- S = Q K^T ----
    float sacc[8][4];
    #pragma unroll
    for (int nf = 0; nf < 8; ++nf)
        #pragma unroll
        for (int e = 0; e < 4; ++e) sacc[nf][e] = 0.f;

    #pragma unroll
    for (int kc = 0; kc < 4; ++kc) {
        const int k0 = kc * 16 + lc * 2;
        uint32_t a[4];
        a[0] = ldpair(&Qs[m * 72 + k0]);
        a[1] = ldpair(&Qs[(m + 8) * 72 + k0]);
        a[2] = ldpair(&Qs[m * 72 + k0 + 8]);
        a[3] = ldpair(&Qs[(m + 8) * 72 + k0 + 8]);
        #pragma unroll
        for (int nf = 0; nf < 8; ++nf) {
            const int n = nf * 8 + lr;
            uint32_t b0 = ldpair(&Ks[n * 72 + k0]);
            uint32_t b1 = ldpair(&Ks[n * 72 + k0 + 8]);
            mma16816(sacc[nf], a, b0, b1);
        }
    }

    // ---- register softmax over rows m (elems 0,1) and m+8 (elems 2,3) ----
    const float sc = 0.125f;  // DIM^-0.5
    float mx0 = -1e30f, mx1 = -1e30f;
    #pragma unroll
    for (int nf = 0; nf < 8; ++nf) {
        mx0 = fmaxf(mx0, fmaxf(sacc[nf][0], sacc[nf][1]));
        mx1 = fmaxf(mx1, fmaxf(sacc[nf][2], sacc[nf][3]));
    }
    mx0 = fmaxf(mx0, __shfl_xor_sync(0xffffffffu, mx0, 1));
    mx0 = fmaxf(mx0, __shfl_xor_sync(0xffffffffu, mx0, 2));
    mx1 = fmaxf(mx1, __shfl_xor_sync(0xffffffffu, mx1, 1));
    mx1 = fmaxf(mx1, __shfl_xor_sync(0xffffffffu, mx1, 2));

    float sum0 = 0.f, sum1 = 0.f;
    #pragma unroll
    for (int nf = 0; nf < 8; ++nf) {
        sacc[nf][0] = __expf(sc * (sacc[nf][0] - mx0));
        sacc[nf][1] = __expf(sc * (sacc[nf][1] - mx0));
        sacc[nf][2] = __expf(sc * (sacc[nf][2] - mx1));
        sacc[nf][3] = __expf(sc * (sacc[nf][3] - mx1));
        sum0 += sacc[nf][0] + sacc[nf][1];
        sum1 += sacc[nf][2] + sacc[nf][3];
    }
    sum0 += __shfl_xor_sync(0xffffffffu, sum0, 1);
    sum0 += __shfl_xor_sync(0xffffffffu, sum0, 2);
    sum1 += __shfl_xor_sync(0xffffffffu, sum1, 1);
    sum1 += __shfl_xor_sync(0xffffffffu, sum1, 2);
    const float inv0 = 1.0f / sum0, inv1 = 1.0f / sum1;

    // ---- P fragments directly from S accumulators (no smem round trip) ----
    // A-frag for k-step kc: k cols kc*16+lc*2 (+8) == S cols nf=2kc (2kc+1)
    uint32_t pf[4][4];
    #pragma unroll
    for (int kc = 0; kc < 4; ++kc) {
        pf[kc][0] = packbf(sacc[2*kc][0] * inv0,     sacc[2*kc][1] * inv0);
        pf[kc][1] = packbf(sacc[2*kc][2] * inv1,     sacc[2*kc][3] * inv1);
        pf[kc][2] = packbf(sacc[2*kc+1][0] * inv0,   sacc[2*kc+1][1] * inv0);
        pf[kc][3] = packbf(sacc[2*kc+1][2] * inv1,   sacc[2*kc+1][3] * inv1);
    }

    // ---- O = P V ----
    float oacc[8][4];
    #pragma unroll
    for (int nf = 0; nf < 8; ++nf)
        #pragma unroll
        for (int e = 0; e < 4; ++e) oacc[nf][e] = 0.f;

    #pragma unroll
    for (int kc = 0; kc < 4; ++kc) {
        const int k0 = kc * 16 + lc * 2;
        #pragma unroll
        for (int nf = 0; nf < 8; ++nf) {
            const int n = nf * 8 + lr;
            uint32_t b0 = ldpair(&Vt[n * 72 + k0]);
            uint32_t b1 = ldpair(&Vt[n * 72 + k0 + 8]);
            mma16816(oacc[nf], pf[kc], b0, b1);
        }
    }

    // ---- residual + store ----
    const float* xb = x + base;
    float* ob = out + base;
    #pragma unroll
    for (int nf = 0; nf < 8; ++nf) {
        const int n = nf * 8 + lc * 2;
        float2 xr0 = *reinterpret_cast<const float2*>(&xb[m * 64 + n]);
        float2 xr1 = *reinterpret_cast<const float2*>(&xb[(m + 8) * 64 + n]);
        float2 o0 = make_float2(oacc[nf][0] + xr0.x, oacc[nf][1] + xr0.y);
        float2 o1 = make_float2(oacc[nf][2] + xr1.x, oacc[nf][3] + xr1.y);
        *reinterpret_cast<float2*>(&ob[m * 64 + n]) = o0;
        *reinterpret_cast<float2*>(&ob[(m + 8) * 64 + n]) = o1;
    }
}

// ---------------------------------------------------------------------------
extern "C" void kernel_launch(void* const* d_in, const int* in_sizes, int n_in,
                              void* d_out, int out_size)
{
    const float* x   = (const float*)d_in[0];
    const float* ctx = (const float*)d_in[1];
    const float* wq  = (const float*)d_in[2];
    const float* bq  = (const float*)d_in[3];
    const float* wk  = (const float*)d_in[4];
    const float* bk  = (const float*)d_in[5];
    const float* wv  = (const float*)d_in[6];
    const float* bv  = (const float*)d_in[7];
    float* out = (float*)d_out;

    conv_q_kernel<<<dim3(NSP / 128, BB), 256>>>(x, wq, bq);

    cudaFuncSetAttribute(conv_kv_kernel,
                         cudaFuncAttributeMaxDynamicSharedMemorySize,
                         KV_SMEM_BYTES);
    conv_kv_kernel<<<dim3(NSP / (KV_TILES * 128), BB), 512, KV_SMEM_BYTES>>>(
        ctx, wk, bk, wv, bv);

    attn_kernel<<<dim3(DD, DIM, BB), 128>>>(x, out);
}

// round 3
// speedup vs baseline: 2.1254x; 1.4014x over previous
#include <cuda_runtime.h>
#include <cuda_bf16.h>
#include <stdint.h>

#define BB   4
#define DIM  64
#define CDIM 128
#define DD   64
#define HH   64
#define WW   64
#define NSP  (DD*HH*WW)
#define HW   (HH*WW)

__device__ __nv_bfloat16 g_q[(size_t)BB * DIM * NSP];
__device__ __nv_bfloat16 g_k[(size_t)BB * DIM * NSP];
__device__ __nv_bfloat16 g_v[(size_t)BB * DIM * NSP];

__device__ __forceinline__ void mma16816(float c[4], const uint32_t a[4],
                                         uint32_t b0, uint32_t b1) {
    asm volatile(
        "mma.sync.aligned.m16n8k16.row.col.f32.bf16.bf16.f32 "
        "{%0,%1,%2,%3}, {%4,%5,%6,%7}, {%8,%9}, {%0,%1,%2,%3};\n"
        : "+f"(c[0]), "+f"(c[1]), "+f"(c[2]), "+f"(c[3])
        : "r"(a[0]), "r"(a[1]), "r"(a[2]), "r"(a[3]), "r"(b0), "r"(b1));
}

__device__ __forceinline__ uint32_t packbf(float a, float b) {
    __nv_bfloat162 p = __floats2bfloat162_rn(a, b);
    return *reinterpret_cast<uint32_t*>(&p);
}

__device__ __forceinline__ uint32_t smaddr(const void* p) {
    return (uint32_t)__cvta_generic_to_shared(p);
}

__device__ __forceinline__ void ldsm4(uint32_t& r0, uint32_t& r1,
                                      uint32_t& r2, uint32_t& r3, uint32_t a) {
    asm volatile("ldmatrix.sync.aligned.m8n8.x4.shared.b16 {%0,%1,%2,%3},[%4];\n"
                 : "=r"(r0), "=r"(r1), "=r"(r2), "=r"(r3) : "r"(a));
}

__device__ __forceinline__ void ldsm4t(uint32_t& r0, uint32_t& r1,
                                       uint32_t& r2, uint32_t& r3, uint32_t a) {
    asm volatile("ldmatrix.sync.aligned.m8n8.x4.trans.shared.b16 {%0,%1,%2,%3},[%4];\n"
                 : "=r"(r0), "=r"(r1), "=r"(r2), "=r"(r3) : "r"(a));
}

// ---------------------------------------------------------------------------
// Pass 1a: Q = Wq[64x64] * X[64 x NSP] + bq. CTA 256 thr, M=64, N=128, K=64.
// Ws [o][c] pitch 72, Xs [c][n] pitch 136 (gmem-native; B frags via ldsm trans)
// ---------------------------------------------------------------------------
__global__ void __launch_bounds__(256) conv_q_kernel(
    const float* __restrict__ x, const float* __restrict__ wq,
    const float* __restrict__ bq)
{
    __shared__ __align__(16) __nv_bfloat16 Ws[64 * 72];
    __shared__ __align__(16) __nv_bfloat16 Xs[64 * 136];
    __shared__ float bs[64];

    const int tid = threadIdx.x;
    const int b  = blockIdx.y;
    const int n0 = blockIdx.x * 128;
    const float* xb = x + (size_t)b * DIM * NSP;

    #pragma unroll
    for (int i = tid; i < 64 * 16; i += 256) {
        const int o = i >> 4, c4 = (i & 15) * 4;
        float4 w = *reinterpret_cast<const float4*>(&wq[o * 64 + c4]);
        *reinterpret_cast<uint2*>(&Ws[o * 72 + c4]) =
            make_uint2(packbf(w.x, w.y), packbf(w.z, w.w));
    }
    if (tid < 64) bs[tid] = bq[tid];
    #pragma unroll
    for (int i = tid; i < 64 * 32; i += 256) {
        const int c = i >> 5, n4 = (i & 31) * 4;
        float4 v = *reinterpret_cast<const float4*>(&xb[(size_t)c * NSP + n0 + n4]);
        *reinterpret_cast<uint2*>(&Xs[c * 136 + n4]) =
            make_uint2(packbf(v.x, v.y), packbf(v.z, v.w));
    }
    __syncthreads();

    const int warp = tid >> 5, lane = tid & 31;
    const int mw = warp >> 1, nw = warp & 1;
    const int lr = lane >> 2, lc = lane & 3;
    const int m = mw * 16 + lr;

    // ldmatrix lane address components
    const int l8  = lane & 7;
    const int lB1 = (lane >> 3) & 1;   // tile bit 1
    const int lB2 = (lane >> 4) & 1;   // tile bit 2

    // A (non-trans): rows m0+lB1*8+l8 of Ws, col chunk lB2*8; +kc*16 cols
    const uint32_t aBase = smaddr(Ws) +
        ((mw * 16 + lB1 * 8 + l8) * 72 + lB2 * 8) * 2;
    // B (trans): rows (k) lB1*8+l8 of Xs, col chunk nw*64 + lB2*8; +kc*16 rows, +nfp*16 cols
    const uint32_t bBase = smaddr(Xs) +
        ((lB1 * 8 + l8) * 136 + nw * 64 + lB2 * 8) * 2;

    float acc[8][4];
    #pragma unroll
    for (int nf = 0; nf < 8; ++nf)
        #pragma unroll
        for (int e = 0; e < 4; ++e) acc[nf][e] = 0.f;

    #pragma unroll
    for (int kc = 0; kc < 4; ++kc) {
        uint32_t a[4];
        ldsm4(a[0], a[1], a[2], a[3], aBase + kc * 32);
        #pragma unroll
        for (int nfp = 0; nfp < 4; ++nfp) {
            uint32_t b0, b1, b2, b3;
            ldsm4t(b0, b1, b2, b3, bBase + kc * 4352 + nfp * 32);
            mma16816(acc[2 * nfp],     a, b0, b1);
            mma16816(acc[2 * nfp + 1], a, b2, b3);
        }
    }

    __nv_bfloat16* qb = g_q + (size_t)b * DIM * NSP;
    const float bi0 = bs[m], bi1 = bs[m + 8];
    #pragma unroll
    for (int nf = 0; nf < 8; ++nf) {
        const int n = nw * 64 + nf * 8 + lc * 2;
        *reinterpret_cast<uint32_t*>(&qb[(size_t)m * NSP + n0 + n]) =
            packbf(acc[nf][0] + bi0, acc[nf][1] + bi0);
        *reinterpret_cast<uint32_t*>(&qb[(size_t)(m + 8) * NSP + n0 + n]) =
            packbf(acc[nf][2] + bi1, acc[nf][3] + bi1);
    }
}

// ---------------------------------------------------------------------------
// Pass 1b: [K;V] = [Wk;Wv][128x128] * CTX + bias. 512 thr, weights resident,
// 4 N-tiles of 128 per CTA. Ws [o][c] pitch 136, Xs [c][n] pitch 136.
// ---------------------------------------------------------------------------
#define KV_TILES 4
#define KV_SMEM_BYTES (2 * 128 * 136 * (int)sizeof(__nv_bfloat16) + 128 * (int)sizeof(float))

__global__ void __launch_bounds__(512) conv_kv_kernel(
    const float* __restrict__ ctx,
    const float* __restrict__ wk, const float* __restrict__ bk,
    const float* __restrict__ wv, const float* __restrict__ bv)
{
    extern __shared__ __align__(16) __nv_bfloat16 sm[];
    __nv_bfloat16* Ws = sm;                 // [o=128][c pitch 136]
    __nv_bfloat16* Xs = sm + 128 * 136;     // [c=128][n pitch 136]
    float* bs = reinterpret_cast<float*>(sm + 2 * 128 * 136);

    const int tid = threadIdx.x;
    const int b = blockIdx.y;
    const float* cb = ctx + (size_t)b * CDIM * NSP;

    #pragma unroll
    for (int i = tid; i < 128 * 32; i += 512) {
        const int o = i >> 5, c4 = (i & 31) * 4;
        const float* src = (o < 64) ? &wk[o * 128 + c4] : &wv[(o - 64) * 128 + c4];
        float4 w = *reinterpret_cast<const float4*>(src);
        *reinterpret_cast<uint2*>(&Ws[o * 136 + c4]) =
            make_uint2(packbf(w.x, w.y), packbf(w.z, w.w));
    }
    if (tid < 128) bs[tid] = (tid < 64) ? bk[tid] : bv[tid - 64];

    const int warp = tid >> 5, lane = tid & 31;
    const int mw = warp & 3, nw = warp >> 2;
    const int lr = lane >> 2, lc = lane & 3;
    const int l8  = lane & 7;
    const int lB1 = (lane >> 3) & 1;
    const int lB2 = (lane >> 4) & 1;

    uint32_t aBase[2];
    #pragma unroll
    for (int mi = 0; mi < 2; ++mi)
        aBase[mi] = smaddr(Ws) +
            ((mw * 32 + mi * 16 + lB1 * 8 + l8) * 136 + lB2 * 8) * 2;
    const uint32_t bBase = smaddr(Xs) +
        ((lB1 * 8 + l8) * 136 + nw * 32 + lB2 * 8) * 2;

    __nv_bfloat16* kb = g_k + (size_t)b * DIM * NSP;
    __nv_bfloat16* vb = g_v + (size_t)b * DIM * NSP;

    for (int t = 0; t < KV_TILES; ++t) {
        const int n0 = blockIdx.x * (KV_TILES * 128) + t * 128;
        #pragma unroll
        for (int i = tid; i < 128 * 32; i += 512) {
            const int c = i >> 5, n4 = (i & 31) * 4;
            float4 v = *reinterpret_cast<const float4*>(&cb[(size_t)c * NSP + n0 + n4]);
            *reinterpret_cast<uint2*>(&Xs[c * 136 + n4]) =
                make_uint2(packbf(v.x, v.y), packbf(v.z, v.w));
        }
        __syncthreads();

        float acc[2][4][4];
        #pragma unroll
        for (int mi = 0; mi < 2; ++mi)
            #pragma unroll
            for (int nf = 0; nf < 4; ++nf)
                #pragma unroll
                for (int e = 0; e < 4; ++e) acc[mi][nf][e] = 0.f;

        #pragma unroll
        for (int kc = 0; kc < 8; ++kc) {
            uint32_t a[2][4];
            ldsm4(a[0][0], a[0][1], a[0][2], a[0][3], aBase[0] + kc * 32);
            ldsm4(a[1][0], a[1][1], a[1][2], a[1][3], aBase[1] + kc * 32);
            #pragma unroll
            for (int nfp = 0; nfp < 2; ++nfp) {
                uint32_t b0, b1, b2, b3;
                ldsm4t(b0, b1, b2, b3, bBase + kc * 4352 + nfp * 32);
                mma16816(acc[0][2 * nfp],     a[0], b0, b1);
                mma16816(acc[1][2 * nfp],     a[1], b0, b1);
                mma16816(acc[0][2 * nfp + 1], a[0], b2, b3);
                mma16816(acc[1][2 * nfp + 1], a[1], b2, b3);
            }
        }

        #pragma unroll
        for (int mi = 0; mi < 2; ++mi) {
            const int m = mw * 32 + mi * 16 + lr;
            const float bi0 = bs[m], bi1 = bs[m + 8];
            __nv_bfloat16* r0 = (m < 64) ? (kb + (size_t)m * NSP)
                                         : (vb + (size_t)(m - 64) * NSP);
            __nv_bfloat16* r1 = (m + 8 < 64) ? (kb + (size_t)(m + 8) * NSP)
                                             : (vb + (size_t)(m + 8 - 64) * NSP);
            #pragma unroll
            for (int nf = 0; nf < 4; ++nf) {
                const int n = nw * 32 + nf * 8 + lc * 2;
                *reinterpret_cast<uint32_t*>(&r0[n0 + n]) =
                    packbf(acc[mi][nf][0] + bi0, acc[mi][nf][1] + bi0);
                *reinterpret_cast<uint32_t*>(&r1[n0 + n]) =
                    packbf(acc[mi][nf][2] + bi1, acc[mi][nf][3] + bi1);
            }
        }
        __syncthreads();
    }
}

// ---------------------------------------------------------------------------
// Pass 2: per-(b,c,d) attention, 128 thr. All tiles staged naturally with
// uint4 copies; fragments via ldmatrix (V transposed by ldmatrix.trans).
// Register softmax; single __syncthreads.
// ---------------------------------------------------------------------------
__global__ void __launch_bounds__(128) attn_kernel(
    const float* __restrict__ x, float* __restrict__ out)
{
    __shared__ __align__(16) __nv_bfloat16 Qs[64 * 72];
    __shared__ __align__(16) __nv_bfloat16 Ks[64 * 72];
    __shared__ __align__(16) __nv_bfloat16 Vs[64 * 72];

    const int tid = threadIdx.x;
    const int d = blockIdx.x, c = blockIdx.y, b = blockIdx.z;
    const size_t base = (((size_t)b * DIM + c) * DD + d) * HW;

    const uint4* qsrc = reinterpret_cast<const uint4*>(g_q + base);
    const uint4* ksrc = reinterpret_cast<const uint4*>(g_k + base);
    const uint4* vsrc = reinterpret_cast<const uint4*>(g_v + base);

    #pragma unroll
    for (int i = tid; i < 512; i += 128) {
        const int h = i >> 3, w8 = (i & 7) * 8;
        *reinterpret_cast<uint4*>(&Qs[h * 72 + w8]) = qsrc[i];
        *reinterpret_cast<uint4*>(&Ks[h * 72 + w8]) = ksrc[i];
        *reinterpret_cast<uint4*>(&Vs[h * 72 + w8]) = vsrc[i];
    }
    __syncthreads();

    const int warp = tid >> 5, lane = tid & 31;
    const int lr = lane >> 2, lc = lane & 3;
    const int m = warp * 16 + lr;
    const int l8  = lane & 7;
    const int lB1 = (lane >> 3) & 1;
    const int lB2 = (lane >> 4) & 1;

    // A (Q, non-trans): rows m..m+15, cols kc*16 + {0,8}
    const uint32_t qBase = smaddr(Qs) +
        ((warp * 16 + lB1 * 8 + l8) * 72 + lB2 * 8) * 2;
    // B (K, non-trans): rows n (g), cols k (w): tiles [(n,k0),(n,k0+8),(n+8,k0),(n+8,k0+8)]
    const uint32_t kBase = smaddr(Ks) +
        ((lB2 * 8 + l8) * 72 + lB1 * 8) * 2;
    // B (V, trans): rows k (g), cols n (w): tiles [(k0,n),(k0+8,n),(k0,n+8),(k0+8,n+8)]
    const uint32_t vBase = smaddr(Vs) +
        ((lB1 * 8 + l8) * 72 + lB2 * 8) * 2;

    // ---- S = Q K^T ----
    float sacc[8][4];
    #pragma unroll
    for (int nf = 0; nf < 8; ++nf)
        #pragma unroll
        for (int e = 0; e < 4; ++e) sacc[nf][e] = 0.f;

    #pragma unroll
    for (int kc = 0; kc < 4; ++kc) {
        uint32_t a[4];
        ldsm4(a[0], a[1], a[2], a[3], qBase + kc * 32);
        #pragma unroll
        for (int nfp = 0; nfp < 4; ++nfp) {
            uint32_t b0, b1, b2, b3;
            ldsm4(b0, b1, b2, b3, kBase + nfp * 2304 + kc * 32);
            mma16816(sacc[2 * nfp],     a, b0, b1);
            mma16816(sacc[2 * nfp + 1], a, b2, b3);
        }
    }

    // ---- register softmax: rows m (elems 0,1) and m+8 (elems 2,3) ----
    const float sc = 0.125f;
    float mx0 = -1e30f, mx1 = -1e30f;
    #pragma unroll
    for (int nf = 0; nf < 8; ++nf) {
        mx0 = fmaxf(mx0, fmaxf(sacc[nf][0], sacc[nf][1]));
        mx1 = fmaxf(mx1, fmaxf(sacc[nf][2], sacc[nf][3]));
    }
    mx0 = fmaxf(mx0, __shfl_xor_sync(0xffffffffu, mx0, 1));
    mx0 = fmaxf(mx0, __shfl_xor_sync(0xffffffffu, mx0, 2));
    mx1 = fmaxf(mx1, __shfl_xor_sync(0xffffffffu, mx1, 1));
    mx1 = fmaxf(mx1, __shfl_xor_sync(0xffffffffu, mx1, 2));

    float sum0 = 0.f, sum1 = 0.f;
    #pragma unroll
    for (int nf = 0; nf < 8; ++nf) {
        sacc[nf][0] = __expf(sc * (sacc[nf][0] - mx0));
        sacc[nf][1] = __expf(sc * (sacc[nf][1] - mx0));
        sacc[nf][2] = __expf(sc * (sacc[nf][2] - mx1));
        sacc[nf][3] = __expf(sc * (sacc[nf][3] - mx1));
        sum0 += sacc[nf][0] + sacc[nf][1];
        sum1 += sacc[nf][2] + sacc[nf][3];
    }
    sum0 += __shfl_xor_sync(0xffffffffu, sum0, 1);
    sum0 += __shfl_xor_sync(0xffffffffu, sum0, 2);
    sum1 += __shfl_xor_sync(0xffffffffu, sum1, 1);
    sum1 += __shfl_xor_sync(0xffffffffu, sum1, 2);
    const float inv0 = 1.0f / sum0, inv1 = 1.0f / sum1;

    // ---- P fragments from S accumulators (C-frag -> A-frag identity) ----
    uint32_t pf[4][4];
    #pragma unroll
    for (int kc = 0; kc < 4; ++kc) {
        pf[kc][0] = packbf(sacc[2*kc][0] * inv0,   sacc[2*kc][1] * inv0);
        pf[kc][1] = packbf(sacc[2*kc][2] * inv1,   sacc[2*kc][3] * inv1);
        pf[kc][2] = packbf(sacc[2*kc+1][0] * inv0, sacc[2*kc+1][1] * inv0);
        pf[kc][3] = packbf(sacc[2*kc+1][2] * inv1, sacc[2*kc+1][3] * inv1);
    }

    // ---- O = P V ----
    float oacc[8][4];
    #pragma unroll
    for (int nf = 0; nf < 8; ++nf)
        #pragma unroll
        for (int e = 0; e < 4; ++e) oacc[nf][e] = 0.f;

    #pragma unroll
    for (int kc = 0; kc < 4; ++kc) {
        #pragma unroll
        for (int nfp = 0; nfp < 4; ++nfp) {
            uint32_t b0, b1, b2, b3;
            ldsm4t(b0, b1, b2, b3, vBase + kc * 2304 + nfp * 32);
            mma16816(oacc[2 * nfp],     pf[kc], b0, b1);
            mma16816(oacc[2 * nfp + 1], pf[kc], b2, b3);
        }
    }

    // ---- residual + store ----
    const float* xb = x + base;
    float* ob = out + base;
    #pragma unroll
    for (int nf = 0; nf < 8; ++nf) {
        const int n = nf * 8 + lc * 2;
        float2 xr0 = *reinterpret_cast<const float2*>(&xb[m * 64 + n]);
        float2 xr1 = *reinterpret_cast<const float2*>(&xb[(m + 8) * 64 + n]);
        float2 o0 = make_float2(oacc[nf][0] + xr0.x, oacc[nf][1] + xr0.y);
        float2 o1 = make_float2(oacc[nf][2] + xr1.x, oacc[nf][3] + xr1.y);
        *reinterpret_cast<float2*>(&ob[m * 64 + n]) = o0;
        *reinterpret_cast<float2*>(&ob[(m + 8) * 64 + n]) = o1;
    }
}

// ---------------------------------------------------------------------------
extern "C" void kernel_launch(void* const* d_in, const int* in_sizes, int n_in,
                              void* d_out, int out_size)
{
    const float* x   = (const float*)d_in[0];
    const float* ctx = (const float*)d_in[1];
    const float* wq  = (const float*)d_in[2];
    const float* bq  = (const float*)d_in[3];
    const float* wk  = (const float*)d_in[4];
    const float* bk  = (const float*)d_in[5];
    const float* wv  = (const float*)d_in[6];
    const float* bv  = (const float*)d_in[7];
    float* out = (float*)d_out;

    conv_q_kernel<<<dim3(NSP / 128, BB), 256>>>(x, wq, bq);

    cudaFuncSetAttribute(conv_kv_kernel,
                         cudaFuncAttributeMaxDynamicSharedMemorySize,
                         KV_SMEM_BYTES);
    conv_kv_kernel<<<dim3(NSP / (KV_TILES * 128), BB), 512, KV_SMEM_BYTES>>>(
        ctx, wk, bk, wv, bv);

    attn_kernel<<<dim3(DD, DIM, BB), 128>>>(x, out);
}

// round 7
// speedup vs baseline: 2.4001x; 1.1293x over previous
#include <cuda_runtime.h>
#include <cuda_bf16.h>
#include <stdint.h>

#define BB   4
#define DIM  64
#define CDIM 128
#define DD   64
#define HH   64
#define WW   64
#define NSP  (DD*HH*WW)
#define HW   (HH*WW)

__device__ __nv_bfloat16 g_q[(size_t)BB * DIM * NSP];
__device__ __nv_bfloat16 g_k[(size_t)BB * DIM * NSP];
__device__ __nv_bfloat16 g_v[(size_t)BB * DIM * NSP];

__device__ __forceinline__ void mma16816(float c[4], const uint32_t a[4],
                                         uint32_t b0, uint32_t b1) {
    asm volatile(
        "mma.sync.aligned.m16n8k16.row.col.f32.bf16.bf16.f32 "
        "{%0,%1,%2,%3}, {%4,%5,%6,%7}, {%8,%9}, {%0,%1,%2,%3};\n"
        : "+f"(c[0]), "+f"(c[1]), "+f"(c[2]), "+f"(c[3])
        : "r"(a[0]), "r"(a[1]), "r"(a[2]), "r"(a[3]), "r"(b0), "r"(b1));
}

__device__ __forceinline__ uint32_t packbf(float a, float b) {
    __nv_bfloat162 p = __floats2bfloat162_rn(a, b);
    return *reinterpret_cast<uint32_t*>(&p);
}

__device__ __forceinline__ uint32_t smaddr(const void* p) {
    return (uint32_t)__cvta_generic_to_shared(p);
}

__device__ __forceinline__ void ldsm4(uint32_t& r0, uint32_t& r1,
                                      uint32_t& r2, uint32_t& r3, uint32_t a) {
    asm volatile("ldmatrix.sync.aligned.m8n8.x4.shared.b16 {%0,%1,%2,%3},[%4];\n"
                 : "=r"(r0), "=r"(r1), "=r"(r2), "=r"(r3) : "r"(a));
}

__device__ __forceinline__ void ldsm4t(uint32_t& r0, uint32_t& r1,
                                       uint32_t& r2, uint32_t& r3, uint32_t a) {
    asm volatile("ldmatrix.sync.aligned.m8n8.x4.trans.shared.b16 {%0,%1,%2,%3},[%4];\n"
                 : "=r"(r0), "=r"(r1), "=r"(r2), "=r"(r3) : "r"(a));
}

__device__ __forceinline__ void stsm4(uint32_t a, uint32_t r0, uint32_t r1,
                                      uint32_t r2, uint32_t r3) {
    asm volatile("stmatrix.sync.aligned.m8n8.x4.shared.b16 [%0],{%1,%2,%3,%4};\n"
                 :: "r"(a), "r"(r0), "r"(r1), "r"(r2), "r"(r3) : "memory");
}

// ---------------------------------------------------------------------------
// Pass 1a: Q = Wq[64x64] * X + bq. 256 thr, weights resident, 4 N-tiles of 128.
// Epilogue: stmatrix -> smem tile -> coalesced STG.128.
// ---------------------------------------------------------------------------
#define QT 4
__global__ void __launch_bounds__(256) conv_q_kernel(
    const float* __restrict__ x, const float* __restrict__ wq,
    const float* __restrict__ bq)
{
    __shared__ __align__(16) __nv_bfloat16 Ws[64 * 72];
    __shared__ __align__(16) __nv_bfloat16 Xs[64 * 136];
    __shared__ __align__(16) __nv_bfloat16 Os[64 * 136];
    __shared__ float bs[64];

    const int tid = threadIdx.x;
    const int b  = blockIdx.y;
    const float* xb = x + (size_t)b * DIM * NSP;
    __nv_bfloat16* qb = g_q + (size_t)b * DIM * NSP;

    // weights once: 64x64 -> 512 8-elem groups, 2 iters
    #pragma unroll
    for (int i = tid; i < 64 * 8; i += 256) {
        const int o = i >> 3, c8 = (i & 7) * 8;
        float4 wa = *reinterpret_cast<const float4*>(&wq[o * 64 + c8]);
        float4 wb = *reinterpret_cast<const float4*>(&wq[o * 64 + c8 + 4]);
        *reinterpret_cast<uint4*>(&Ws[o * 72 + c8]) =
            make_uint4(packbf(wa.x, wa.y), packbf(wa.z, wa.w),
                       packbf(wb.x, wb.y), packbf(wb.z, wb.w));
    }
    if (tid < 64) bs[tid] = bq[tid];
    __syncthreads();   // bias/weights visible to ALL warps before bs[] reads

    const int warp = tid >> 5, lane = tid & 31;
    const int mw = warp >> 1, nw = warp & 1;
    const int lr = lane >> 2;
    const int l8  = lane & 7;
    const int lB1 = (lane >> 3) & 1;
    const int lB2 = (lane >> 4) & 1;
    const int m = mw * 16 + lr;

    const uint32_t aBase = smaddr(Ws) +
        ((mw * 16 + lB1 * 8 + l8) * 72 + lB2 * 8) * 2;
    const uint32_t bBase = smaddr(Xs) +
        ((lB1 * 8 + l8) * 136 + nw * 64 + lB2 * 8) * 2;
    const uint32_t oBase = smaddr(Os) +
        ((mw * 16 + lB1 * 8 + l8) * 136 + nw * 64 + lB2 * 8) * 2;

    const float bi0 = bs[m], bi1 = bs[m + 8];

    for (int t = 0; t < QT; ++t) {
        const int n0 = blockIdx.x * (QT * 128) + t * 128;
        // stage X: 64ch x 128n, 1024 8-elem groups, 4 iters
        #pragma unroll
        for (int i = tid; i < 64 * 16; i += 256) {
            const int c = i >> 4, n8 = (i & 15) * 8;
            float4 va = *reinterpret_cast<const float4*>(&xb[(size_t)c * NSP + n0 + n8]);
            float4 vb = *reinterpret_cast<const float4*>(&xb[(size_t)c * NSP + n0 + n8 + 4]);
            *reinterpret_cast<uint4*>(&Xs[c * 136 + n8]) =
                make_uint4(packbf(va.x, va.y), packbf(va.z, va.w),
                           packbf(vb.x, vb.y), packbf(vb.z, vb.w));
        }
        __syncthreads();

        float acc[8][4];
        #pragma unroll
        for (int nf = 0; nf < 8; ++nf)
            #pragma unroll
            for (int e = 0; e < 4; ++e) acc[nf][e] = 0.f;

        #pragma unroll
        for (int kc = 0; kc < 4; ++kc) {
            uint32_t a[4];
            ldsm4(a[0], a[1], a[2], a[3], aBase + kc * 32);
            #pragma unroll
            for (int nfp = 0; nfp < 4; ++nfp) {
                uint32_t b0, b1, b2, b3;
                ldsm4t(b0, b1, b2, b3, bBase + kc * 4352 + nfp * 32);
                mma16816(acc[2 * nfp],     a, b0, b1);
                mma16816(acc[2 * nfp + 1], a, b2, b3);
            }
        }

        // epilogue: bias + stmatrix into Os
        #pragma unroll
        for (int nfp = 0; nfp < 4; ++nfp) {
            stsm4(oBase + nfp * 32,
                  packbf(acc[2*nfp][0] + bi0,   acc[2*nfp][1] + bi0),
                  packbf(acc[2*nfp][2] + bi1,   acc[2*nfp][3] + bi1),
                  packbf(acc[2*nfp+1][0] + bi0, acc[2*nfp+1][1] + bi0),
                  packbf(acc[2*nfp+1][2] + bi1, acc[2*nfp+1][3] + bi1));
        }
        __syncthreads();

        // coalesced store: 64 rows x 16 uint4, 4 iters
        #pragma unroll
        for (int i = tid; i < 64 * 16; i += 256) {
            const int row = i >> 4, q8 = (i & 15) * 8;
            uint4 v = *reinterpret_cast<const uint4*>(&Os[row * 136 + q8]);
            *reinterpret_cast<uint4*>(&qb[(size_t)row * NSP + n0 + q8]) = v;
        }
        __syncthreads();
    }
}

// ---------------------------------------------------------------------------
// Pass 1b: [K;V] = [Wk;Wv][128x128]*CTX + bias. 512 thr, weights resident,
// 4 N-tiles of 128. Same stmatrix epilogue. Dynamic smem ~103KB.
// ---------------------------------------------------------------------------
#define KVT 4
#define KV_SMEM_BYTES (3 * 128 * 136 * (int)sizeof(__nv_bfloat16) + 128 * (int)sizeof(float))

__global__ void __launch_bounds__(512) conv_kv_kernel(
    const float* __restrict__ ctx,
    const float* __restrict__ wk, const float* __restrict__ bk,
    const float* __restrict__ wv, const float* __restrict__ bv)
{
    extern __shared__ __align__(16) __nv_bfloat16 sm[];
    __nv_bfloat16* Ws = sm;                  // [o=128][c pitch 136]
    __nv_bfloat16* Xs = sm + 128 * 136;      // [c=128][n pitch 136]
    __nv_bfloat16* Os = sm + 2 * 128 * 136;  // [o=128][n pitch 136]
    float* bs = reinterpret_cast<float*>(sm + 3 * 128 * 136);

    const int tid = threadIdx.x;
    const int b = blockIdx.y;
    const float* cb = ctx + (size_t)b * CDIM * NSP;

    #pragma unroll
    for (int i = tid; i < 128 * 16; i += 512) {
        const int o = i >> 4, c8 = (i & 15) * 8;
        const float* src = (o < 64) ? &wk[o * 128 + c8] : &wv[(o - 64) * 128 + c8];
        float4 wa = *reinterpret_cast<const float4*>(src);
        float4 wb = *reinterpret_cast<const float4*>(src + 4);
        *reinterpret_cast<uint4*>(&Ws[o * 136 + c8]) =
            make_uint4(packbf(wa.x, wa.y), packbf(wa.z, wa.w),
                       packbf(wb.x, wb.y), packbf(wb.z, wb.w));
    }
    if (tid < 128) bs[tid] = (tid < 64) ? bk[tid] : bv[tid - 64];

    const int warp = tid >> 5, lane = tid & 31;
    const int mw = warp & 3, nw = warp >> 2;
    const int lr = lane >> 2;
    const int l8  = lane & 7;
    const int lB1 = (lane >> 3) & 1;
    const int lB2 = (lane >> 4) & 1;

    uint32_t aBase[2], oBase[2];
    #pragma unroll
    for (int mi = 0; mi < 2; ++mi) {
        aBase[mi] = smaddr(Ws) +
            ((mw * 32 + mi * 16 + lB1 * 8 + l8) * 136 + lB2 * 8) * 2;
        oBase[mi] = smaddr(Os) +
            ((mw * 32 + mi * 16 + lB1 * 8 + l8) * 136 + nw * 32 + lB2 * 8) * 2;
    }
    const uint32_t bBase = smaddr(Xs) +
        ((lB1 * 8 + l8) * 136 + nw * 32 + lB2 * 8) * 2;

    __nv_bfloat16* kb = g_k + (size_t)b * DIM * NSP;
    __nv_bfloat16* vb = g_v + (size_t)b * DIM * NSP;

    for (int t = 0; t < KVT; ++t) {
        const int n0 = blockIdx.x * (KVT * 128) + t * 128;
        #pragma unroll
        for (int i = tid; i < 128 * 16; i += 512) {
            const int c = i >> 4, n8 = (i & 15) * 8;
            float4 va = *reinterpret_cast<const float4*>(&cb[(size_t)c * NSP + n0 + n8]);
            float4 vv = *reinterpret_cast<const float4*>(&cb[(size_t)c * NSP + n0 + n8 + 4]);
            *reinterpret_cast<uint4*>(&Xs[c * 136 + n8]) =
                make_uint4(packbf(va.x, va.y), packbf(va.z, va.w),
                           packbf(vv.x, vv.y), packbf(vv.z, vv.w));
        }
        __syncthreads();

        float acc[2][4][4];
        #pragma unroll
        for (int mi = 0; mi < 2; ++mi)
            #pragma unroll
            for (int nf = 0; nf < 4; ++nf)
                #pragma unroll
                for (int e = 0; e < 4; ++e) acc[mi][nf][e] = 0.f;

        #pragma unroll
        for (int kc = 0; kc < 8; ++kc) {
            uint32_t a[2][4];
            ldsm4(a[0][0], a[0][1], a[0][2], a[0][3], aBase[0] + kc * 32);
            ldsm4(a[1][0], a[1][1], a[1][2], a[1][3], aBase[1] + kc * 32);
            #pragma unroll
            for (int nfp = 0; nfp < 2; ++nfp) {
                uint32_t b0, b1, b2, b3;
                ldsm4t(b0, b1, b2, b3, bBase + kc * 4352 + nfp * 32);
                mma16816(acc[0][2 * nfp],     a[0], b0, b1);
                mma16816(acc[1][2 * nfp],     a[1], b0, b1);
                mma16816(acc[0][2 * nfp + 1], a[0], b2, b3);
                mma16816(acc[1][2 * nfp + 1], a[1], b2, b3);
            }
        }

        #pragma unroll
        for (int mi = 0; mi < 2; ++mi) {
            const int m = mw * 32 + mi * 16 + lr;
            const float bi0 = bs[m], bi1 = bs[m + 8];
            #pragma unroll
            for (int nfp = 0; nfp < 2; ++nfp) {
                stsm4(oBase[mi] + nfp * 32,
                      packbf(acc[mi][2*nfp][0] + bi0,   acc[mi][2*nfp][1] + bi0),
                      packbf(acc[mi][2*nfp][2] + bi1,   acc[mi][2*nfp][3] + bi1),
                      packbf(acc[mi][2*nfp+1][0] + bi0, acc[mi][2*nfp+1][1] + bi0),
                      packbf(acc[mi][2*nfp+1][2] + bi1, acc[mi][2*nfp+1][3] + bi1));
            }
        }
        __syncthreads();

        #pragma unroll
        for (int i = tid; i < 128 * 16; i += 512) {
            const int row = i >> 4, q8 = (i & 15) * 8;
            uint4 v = *reinterpret_cast<const uint4*>(&Os[row * 136 + q8]);
            __nv_bfloat16* dst = (row < 64) ? (kb + (size_t)row * NSP)
                                            : (vb + (size_t)(row - 64) * NSP);
            *reinterpret_cast<uint4*>(&dst[n0 + q8]) = v;
        }
        __syncthreads();
    }
}

// ---------------------------------------------------------------------------
// Pass 2: per-(b,c,d) attention, 128 thr. Register softmax.
// Epilogue: O staged fp32 in smem (overlapping Q/K region), coalesced
// LDG.128(x) + STG.128(out).
// ---------------------------------------------------------------------------
__global__ void __launch_bounds__(128) attn_kernel(
    const float* __restrict__ x, float* __restrict__ out)
{
    __shared__ __align__(16) char smbuf[3 * 64 * 72 * 2];
    __nv_bfloat16* Qs = reinterpret_cast<__nv_bfloat16*>(smbuf);
    __nv_bfloat16* Ks = Qs + 64 * 72;
    __nv_bfloat16* Vs = Qs + 2 * 64 * 72;
    float* Of = reinterpret_cast<float*>(smbuf);   // 64x68 fp32, overlaps Qs+Ks

    const int tid = threadIdx.x;
    const int d = blockIdx.x, c = blockIdx.y, b = blockIdx.z;
    const size_t base = (((size_t)b * DIM + c) * DD + d) * HW;

    const uint4* qsrc = reinterpret_cast<const uint4*>(g_q + base);
    const uint4* ksrc = reinterpret_cast<const uint4*>(g_k + base);
    const uint4* vsrc = reinterpret_cast<const uint4*>(g_v + base);

    #pragma unroll
    for (int i = tid; i < 512; i += 128) {
        const int h = i >> 3, w8 = (i & 7) * 8;
        *reinterpret_cast<uint4*>(&Qs[h * 72 + w8]) = qsrc[i];
        *reinterpret_cast<uint4*>(&Ks[h * 72 + w8]) = ksrc[i];
        *reinterpret_cast<uint4*>(&Vs[h * 72 + w8]) = vsrc[i];
    }
    __syncthreads();

    const int warp = tid >> 5, lane = tid & 31;
    const int lr = lane >> 2, lc = lane & 3;
    const int m = warp * 16 + lr;
    const int l8  = lane & 7;
    const int lB1 = (lane >> 3) & 1;
    const int lB2 = (lane >> 4) & 1;

    const uint32_t qBase = smaddr(Qs) +
        ((warp * 16 + lB1 * 8 + l8) * 72 + lB2 * 8) * 2;
    const uint32_t kBase = smaddr(Ks) +
        ((lB2 * 8 + l8) * 72 + lB1 * 8) * 2;
    const uint32_t vBase = smaddr(Vs) +
        ((lB1 * 8 + l8) * 72 + lB2 * 8) * 2;

    // ---- S = Q K^T ----
    float sacc[8][4];
    #pragma unroll
    for (int nf = 0; nf < 8; ++nf)
        #pragma unroll
        for (int e = 0; e < 4; ++e) sacc[nf][e] = 0.f;

    #pragma unroll
    for (int kc = 0; kc < 4; ++kc) {
        uint32_t a[4];
        ldsm4(a[0], a[1], a[2], a[3], qBase + kc * 32);
        #pragma unroll
        for (int nfp = 0; nfp < 4; ++nfp) {
            uint32_t b0, b1, b2, b3;
            ldsm4(b0, b1, b2, b3, kBase + nfp * 2304 + kc * 32);
            mma16816(sacc[2 * nfp],     a, b0, b1);
            mma16816(sacc[2 * nfp + 1], a, b2, b3);
        }
    }

    // ---- register softmax ----
    const float sc = 0.125f;
    float mx0 = -1e30f, mx1 = -1e30f;
    #pragma unroll
    for (int nf = 0; nf < 8; ++nf) {
        mx0 = fmaxf(mx0, fmaxf(sacc[nf][0], sacc[nf][1]));
        mx1 = fmaxf(mx1, fmaxf(sacc[nf][2], sacc[nf][3]));
    }
    mx0 = fmaxf(mx0, __shfl_xor_sync(0xffffffffu, mx0, 1));
    mx0 = fmaxf(mx0, __shfl_xor_sync(0xffffffffu, mx0, 2));
    mx1 = fmaxf(mx1, __shfl_xor_sync(0xffffffffu, mx1, 1));
    mx1 = fmaxf(mx1, __shfl_xor_sync(0xffffffffu, mx1, 2));

    float sum0 = 0.f, sum1 = 0.f;
    #pragma unroll
    for (int nf = 0; nf < 8; ++nf) {
        sacc[nf][0] = __expf(sc * (sacc[nf][0] - mx0));
        sacc[nf][1] = __expf(sc * (sacc[nf][1] - mx0));
        sacc[nf][2] = __expf(sc * (sacc[nf][2] - mx1));
        sacc[nf][3] = __expf(sc * (sacc[nf][3] - mx1));
        sum0 += sacc[nf][0] + sacc[nf][1];
        sum1 += sacc[nf][2] + sacc[nf][3];
    }
    sum0 += __shfl_xor_sync(0xffffffffu, sum0, 1);
    sum0 += __shfl_xor_sync(0xffffffffu, sum0, 2);
    sum1 += __shfl_xor_sync(0xffffffffu, sum1, 1);
    sum1 += __shfl_xor_sync(0xffffffffu, sum1, 2);
    const float inv0 = 1.0f / sum0, inv1 = 1.0f / sum1;

    // ---- P fragments (C-frag -> A-frag identity) ----
    uint32_t pf[4][4];
    #pragma unroll
    for (int kc = 0; kc < 4; ++kc) {
        pf[kc][0] = packbf(sacc[2*kc][0] * inv0,   sacc[2*kc][1] * inv0);
        pf[kc][1] = packbf(sacc[2*kc][2] * inv1,   sacc[2*kc][3] * inv1);
        pf[kc][2] = packbf(sacc[2*kc+1][0] * inv0, sacc[2*kc+1][1] * inv0);
        pf[kc][3] = packbf(sacc[2*kc+1][2] * inv1, sacc[2*kc+1][3] * inv1);
    }

    // ---- O = P V ----
    float oacc[8][4];
    #pragma unroll
    for (int nf = 0; nf < 8; ++nf)
        #pragma unroll
        for (int e = 0; e < 4; ++e) oacc[nf][e] = 0.f;

    #pragma unroll
    for (int kc = 0; kc < 4; ++kc) {
        #pragma unroll
        for (int nfp = 0; nfp < 4; ++nfp) {
            uint32_t b0, b1, b2, b3;
            ldsm4t(b0, b1, b2, b3, vBase + kc * 2304 + nfp * 32);
            mma16816(oacc[2 * nfp],     pf[kc], b0, b1);
            mma16816(oacc[2 * nfp + 1], pf[kc], b2, b3);
        }
    }

    // ---- stage O in smem (clobbers Qs/Ks; all mma reads are done) ----
    __syncthreads();
    #pragma unroll
    for (int nf = 0; nf < 8; ++nf) {
        const int n = nf * 8 + lc * 2;
        *reinterpret_cast<float2*>(&Of[m * 68 + n]) =
            make_float2(oacc[nf][0], oacc[nf][1]);
        *reinterpret_cast<float2*>(&Of[(m + 8) * 68 + n]) =
            make_float2(oacc[nf][2], oacc[nf][3]);
    }
    __syncthreads();

    // ---- coalesced residual + store: 64 rows x 16 float4 ----
    const float* xb = x + base;
    float* ob = out + base;
    #pragma unroll
    for (int i = tid; i < 64 * 16; i += 128) {
        const int row = i >> 4, q4 = (i & 15) * 4;
        float4 o = *reinterpret_cast<const float4*>(&Of[row * 68 + q4]);
        float4 xr = *reinterpret_cast<const float4*>(&xb[row * 64 + q4]);
        o.x += xr.x; o.y += xr.y; o.z += xr.z; o.w += xr.w;
        *reinterpret_cast<float4*>(&ob[row * 64 + q4]) = o;
    }
}

// ---------------------------------------------------------------------------
extern "C" void kernel_launch(void* const* d_in, const int* in_sizes, int n_in,
                              void* d_out, int out_size)
{
    const float* x   = (const float*)d_in[0];
    const float* ctx = (const float*)d_in[1];
    const float* wq  = (const float*)d_in[2];
    const float* bq  = (const float*)d_in[3];
    const float* wk  = (const float*)d_in[4];
    const float* bk  = (const float*)d_in[5];
    const float* wv  = (const float*)d_in[6];
    const float* bv  = (const float*)d_in[7];
    float* out = (float*)d_out;

    conv_q_kernel<<<dim3(NSP / (QT * 128), BB), 256>>>(x, wq, bq);

    cudaFuncSetAttribute(conv_kv_kernel,
                         cudaFuncAttributeMaxDynamicSharedMemorySize,
                         KV_SMEM_BYTES);
    conv_kv_kernel<<<dim3(NSP / (KVT * 128), BB), 512, KV_SMEM_BYTES>>>(
        ctx, wk, bk, wv, bv);

    attn_kernel<<<dim3(DD, DIM, BB), 128>>>(x, out);
}

// round 8
// speedup vs baseline: 2.5582x; 1.0659x over previous
#include <cuda_runtime.h>
#include <cuda_bf16.h>
#include <stdint.h>

#define BB   4
#define DIM  64
#define CDIM 128
#define DD   64
#define HH   64
#define WW   64
#define NSP  (DD*HH*WW)
#define HW   (HH*WW)

__device__ __nv_bfloat16 g_q[(size_t)BB * DIM * NSP];
__device__ __nv_bfloat16 g_k[(size_t)BB * DIM * NSP];
__device__ __nv_bfloat16 g_v[(size_t)BB * DIM * NSP];

__device__ __forceinline__ void mma16816(float c[4], const uint32_t a[4],
                                         uint32_t b0, uint32_t b1) {
    asm volatile(
        "mma.sync.aligned.m16n8k16.row.col.f32.bf16.bf16.f32 "
        "{%0,%1,%2,%3}, {%4,%5,%6,%7}, {%8,%9}, {%0,%1,%2,%3};\n"
        : "+f"(c[0]), "+f"(c[1]), "+f"(c[2]), "+f"(c[3])
        : "r"(a[0]), "r"(a[1]), "r"(a[2]), "r"(a[3]), "r"(b0), "r"(b1));
}

__device__ __forceinline__ uint32_t packbf(float a, float b) {
    __nv_bfloat162 p = __floats2bfloat162_rn(a, b);
    return *reinterpret_cast<uint32_t*>(&p);
}

__device__ __forceinline__ uint32_t smaddr(const void* p) {
    return (uint32_t)__cvta_generic_to_shared(p);
}

__device__ __forceinline__ void ldsm4(uint32_t& r0, uint32_t& r1,
                                      uint32_t& r2, uint32_t& r3, uint32_t a) {
    asm volatile("ldmatrix.sync.aligned.m8n8.x4.shared.b16 {%0,%1,%2,%3},[%4];\n"
                 : "=r"(r0), "=r"(r1), "=r"(r2), "=r"(r3) : "r"(a));
}

__device__ __forceinline__ void ldsm4t(uint32_t& r0, uint32_t& r1,
                                       uint32_t& r2, uint32_t& r3, uint32_t a) {
    asm volatile("ldmatrix.sync.aligned.m8n8.x4.trans.shared.b16 {%0,%1,%2,%3},[%4];\n"
                 : "=r"(r0), "=r"(r1), "=r"(r2), "=r"(r3) : "r"(a));
}

__device__ __forceinline__ void stsm4(uint32_t a, uint32_t r0, uint32_t r1,
                                      uint32_t r2, uint32_t r3) {
    asm volatile("stmatrix.sync.aligned.m8n8.x4.shared.b16 [%0],{%1,%2,%3,%4};\n"
                 :: "r"(a), "r"(r0), "r"(r1), "r"(r2), "r"(r3) : "memory");
}

__device__ __forceinline__ void cpasync16(uint32_t s, const void* g) {
    asm volatile("cp.async.cg.shared.global [%0], [%1], 16;\n" :: "r"(s), "l"(g));
}

// ---------------------------------------------------------------------------
// Pass 1a: Q = Wq[64x64] * X + bq. 256 thr, weights resident, 4 N-tiles of 128,
// register-prefetch pipeline on X tiles. stmatrix epilogue + coalesced STG.128.
// ---------------------------------------------------------------------------
#define QT 4
__global__ void __launch_bounds__(256) conv_q_kernel(
    const float* __restrict__ x, const float* __restrict__ wq,
    const float* __restrict__ bq)
{
    __shared__ __align__(16) __nv_bfloat16 Ws[64 * 72];
    __shared__ __align__(16) __nv_bfloat16 Xs[64 * 136];
    __shared__ __align__(16) __nv_bfloat16 Os[64 * 136];
    __shared__ float bs[64];

    const int tid = threadIdx.x;
    const int b  = blockIdx.y;
    const float* xb = x + (size_t)b * DIM * NSP;
    __nv_bfloat16* qb = g_q + (size_t)b * DIM * NSP;

    #pragma unroll
    for (int i = tid; i < 64 * 8; i += 256) {
        const int o = i >> 3, c8 = (i & 7) * 8;
        float4 wa = *reinterpret_cast<const float4*>(&wq[o * 64 + c8]);
        float4 wb = *reinterpret_cast<const float4*>(&wq[o * 64 + c8 + 4]);
        *reinterpret_cast<uint4*>(&Ws[o * 72 + c8]) =
            make_uint4(packbf(wa.x, wa.y), packbf(wa.z, wa.w),
                       packbf(wb.x, wb.y), packbf(wb.z, wb.w));
    }
    if (tid < 64) bs[tid] = bq[tid];

    const int warp = tid >> 5, lane = tid & 31;
    const int mw = warp >> 1, nw = warp & 1;
    const int lr = lane >> 2;
    const int l8  = lane & 7;
    const int lB1 = (lane >> 3) & 1;
    const int lB2 = (lane >> 4) & 1;
    const int m = mw * 16 + lr;

    const uint32_t aBase = smaddr(Ws) +
        ((mw * 16 + lB1 * 8 + l8) * 72 + lB2 * 8) * 2;
    const uint32_t bBase = smaddr(Xs) +
        ((lB1 * 8 + l8) * 136 + nw * 64 + lB2 * 8) * 2;
    const uint32_t oBase = smaddr(Os) +
        ((mw * 16 + lB1 * 8 + l8) * 136 + nw * 64 + lB2 * 8) * 2;

    // per-thread staging coords (4 chunks of 8 floats)
    int sc_[4], sn_[4];
    #pragma unroll
    for (int j = 0; j < 4; ++j) {
        const int i = tid + j * 256;
        sc_[j] = i >> 4;
        sn_[j] = (i & 15) * 8;
    }

    float4 r[2][4][2];
    const int tile0 = blockIdx.x * (QT * 128);
    // prologue: prefetch tile 0
    #pragma unroll
    for (int j = 0; j < 4; ++j) {
        const float* src = &xb[(size_t)sc_[j] * NSP + tile0 + sn_[j]];
        r[0][j][0] = *reinterpret_cast<const float4*>(src);
        r[0][j][1] = *reinterpret_cast<const float4*>(src + 4);
    }
    __syncthreads();   // weights + bias visible

    const float bi0 = bs[m], bi1 = bs[m + 8];

    #pragma unroll
    for (int t = 0; t < QT; ++t) {
        const int n0 = tile0 + t * 128;
        const int cur = t & 1, nxt = cur ^ 1;
        // store prefetched tile into Xs (converted)
        #pragma unroll
        for (int j = 0; j < 4; ++j) {
            float4 va = r[cur][j][0], vb = r[cur][j][1];
            *reinterpret_cast<uint4*>(&Xs[sc_[j] * 136 + sn_[j]]) =
                make_uint4(packbf(va.x, va.y), packbf(va.z, va.w),
                           packbf(vb.x, vb.y), packbf(vb.z, vb.w));
        }
        __syncthreads();

        // prefetch next tile (overlaps with mma below)
        if (t + 1 < QT) {
            #pragma unroll
            for (int j = 0; j < 4; ++j) {
                const float* src = &xb[(size_t)sc_[j] * NSP + n0 + 128 + sn_[j]];
                r[nxt][j][0] = *reinterpret_cast<const float4*>(src);
                r[nxt][j][1] = *reinterpret_cast<const float4*>(src + 4);
            }
        }

        float acc[8][4];
        #pragma unroll
        for (int nf = 0; nf < 8; ++nf)
            #pragma unroll
            for (int e = 0; e < 4; ++e) acc[nf][e] = 0.f;

        #pragma unroll
        for (int kc = 0; kc < 4; ++kc) {
            uint32_t a[4];
            ldsm4(a[0], a[1], a[2], a[3], aBase + kc * 32);
            #pragma unroll
            for (int nfp = 0; nfp < 4; ++nfp) {
                uint32_t b0, b1, b2, b3;
                ldsm4t(b0, b1, b2, b3, bBase + kc * 4352 + nfp * 32);
                mma16816(acc[2 * nfp],     a, b0, b1);
                mma16816(acc[2 * nfp + 1], a, b2, b3);
            }
        }

        #pragma unroll
        for (int nfp = 0; nfp < 4; ++nfp) {
            stsm4(oBase + nfp * 32,
                  packbf(acc[2*nfp][0] + bi0,   acc[2*nfp][1] + bi0),
                  packbf(acc[2*nfp][2] + bi1,   acc[2*nfp][3] + bi1),
                  packbf(acc[2*nfp+1][0] + bi0, acc[2*nfp+1][1] + bi0),
                  packbf(acc[2*nfp+1][2] + bi1, acc[2*nfp+1][3] + bi1));
        }
        __syncthreads();

        #pragma unroll
        for (int i = tid; i < 64 * 16; i += 256) {
            const int row = i >> 4, q8 = (i & 15) * 8;
            uint4 v = *reinterpret_cast<const uint4*>(&Os[row * 136 + q8]);
            *reinterpret_cast<uint4*>(&qb[(size_t)row * NSP + n0 + q8]) = v;
        }
        __syncthreads();
    }
}

// ---------------------------------------------------------------------------
// Pass 1b: [K;V] = [Wk;Wv][128x128]*CTX + bias. 512 thr, weights resident,
// 4 N-tiles of 128, register-prefetch pipeline. stmatrix epilogue.
// ---------------------------------------------------------------------------
#define KVT 4
#define KV_SMEM_BYTES (3 * 128 * 136 * (int)sizeof(__nv_bfloat16) + 128 * (int)sizeof(float))

__global__ void __launch_bounds__(512) conv_kv_kernel(
    const float* __restrict__ ctx,
    const float* __restrict__ wk, const float* __restrict__ bk,
    const float* __restrict__ wv, const float* __restrict__ bv)
{
    extern __shared__ __align__(16) __nv_bfloat16 sm[];
    __nv_bfloat16* Ws = sm;                  // [o=128][c pitch 136]
    __nv_bfloat16* Xs = sm + 128 * 136;      // [c=128][n pitch 136]
    __nv_bfloat16* Os = sm + 2 * 128 * 136;  // [o=128][n pitch 136]
    float* bs = reinterpret_cast<float*>(sm + 3 * 128 * 136);

    const int tid = threadIdx.x;
    const int b = blockIdx.y;
    const float* cb = ctx + (size_t)b * CDIM * NSP;

    #pragma unroll
    for (int i = tid; i < 128 * 16; i += 512) {
        const int o = i >> 4, c8 = (i & 15) * 8;
        const float* src = (o < 64) ? &wk[o * 128 + c8] : &wv[(o - 64) * 128 + c8];
        float4 wa = *reinterpret_cast<const float4*>(src);
        float4 wb = *reinterpret_cast<const float4*>(src + 4);
        *reinterpret_cast<uint4*>(&Ws[o * 136 + c8]) =
            make_uint4(packbf(wa.x, wa.y), packbf(wa.z, wa.w),
                       packbf(wb.x, wb.y), packbf(wb.z, wb.w));
    }
    if (tid < 128) bs[tid] = (tid < 64) ? bk[tid] : bv[tid - 64];

    const int warp = tid >> 5, lane = tid & 31;
    const int mw = warp & 3, nw = warp >> 2;
    const int lr = lane >> 2;
    const int l8  = lane & 7;
    const int lB1 = (lane >> 3) & 1;
    const int lB2 = (lane >> 4) & 1;

    uint32_t aBase[2], oBase[2];
    #pragma unroll
    for (int mi = 0; mi < 2; ++mi) {
        aBase[mi] = smaddr(Ws) +
            ((mw * 32 + mi * 16 + lB1 * 8 + l8) * 136 + lB2 * 8) * 2;
        oBase[mi] = smaddr(Os) +
            ((mw * 32 + mi * 16 + lB1 * 8 + l8) * 136 + nw * 32 + lB2 * 8) * 2;
    }
    const uint32_t bBase = smaddr(Xs) +
        ((lB1 * 8 + l8) * 136 + nw * 32 + lB2 * 8) * 2;

    __nv_bfloat16* kb = g_k + (size_t)b * DIM * NSP;
    __nv_bfloat16* vb = g_v + (size_t)b * DIM * NSP;

    // per-thread staging coords (4 chunks of 8 floats)
    int sc_[4], sn_[4];
    #pragma unroll
    for (int j = 0; j < 4; ++j) {
        const int i = tid + j * 512;
        sc_[j] = i >> 4;
        sn_[j] = (i & 15) * 8;
    }

    float4 r[2][4][2];
    const int tile0 = blockIdx.x * (KVT * 128);
    #pragma unroll
    for (int j = 0; j < 4; ++j) {
        const float* src = &cb[(size_t)sc_[j] * NSP + tile0 + sn_[j]];
        r[0][j][0] = *reinterpret_cast<const float4*>(src);
        r[0][j][1] = *reinterpret_cast<const float4*>(src + 4);
    }
    __syncthreads();

    #pragma unroll
    for (int t = 0; t < KVT; ++t) {
        const int n0 = tile0 + t * 128;
        const int cur = t & 1, nxt = cur ^ 1;
        #pragma unroll
        for (int j = 0; j < 4; ++j) {
            float4 va = r[cur][j][0], vv = r[cur][j][1];
            *reinterpret_cast<uint4*>(&Xs[sc_[j] * 136 + sn_[j]]) =
                make_uint4(packbf(va.x, va.y), packbf(va.z, va.w),
                           packbf(vv.x, vv.y), packbf(vv.z, vv.w));
        }
        __syncthreads();

        if (t + 1 < KVT) {
            #pragma unroll
            for (int j = 0; j < 4; ++j) {
                const float* src = &cb[(size_t)sc_[j] * NSP + n0 + 128 + sn_[j]];
                r[nxt][j][0] = *reinterpret_cast<const float4*>(src);
                r[nxt][j][1] = *reinterpret_cast<const float4*>(src + 4);
            }
        }

        float acc[2][4][4];
        #pragma unroll
        for (int mi = 0; mi < 2; ++mi)
            #pragma unroll
            for (int nf = 0; nf < 4; ++nf)
                #pragma unroll
                for (int e = 0; e < 4; ++e) acc[mi][nf][e] = 0.f;

        #pragma unroll
        for (int kc = 0; kc < 8; ++kc) {
            uint32_t a[2][4];
            ldsm4(a[0][0], a[0][1], a[0][2], a[0][3], aBase[0] + kc * 32);
            ldsm4(a[1][0], a[1][1], a[1][2], a[1][3], aBase[1] + kc * 32);
            #pragma unroll
            for (int nfp = 0; nfp < 2; ++nfp) {
                uint32_t b0, b1, b2, b3;
                ldsm4t(b0, b1, b2, b3, bBase + kc * 4352 + nfp * 32);
                mma16816(acc[0][2 * nfp],     a[0], b0, b1);
                mma16816(acc[1][2 * nfp],     a[1], b0, b1);
                mma16816(acc[0][2 * nfp + 1], a[0], b2, b3);
                mma16816(acc[1][2 * nfp + 1], a[1], b2, b3);
            }
        }

        #pragma unroll
        for (int mi = 0; mi < 2; ++mi) {
            const int m = mw * 32 + mi * 16 + lr;
            const float bi0 = bs[m], bi1 = bs[m + 8];
            #pragma unroll
            for (int nfp = 0; nfp < 2; ++nfp) {
                stsm4(oBase[mi] + nfp * 32,
                      packbf(acc[mi][2*nfp][0] + bi0,   acc[mi][2*nfp][1] + bi0),
                      packbf(acc[mi][2*nfp][2] + bi1,   acc[mi][2*nfp][3] + bi1),
                      packbf(acc[mi][2*nfp+1][0] + bi0, acc[mi][2*nfp+1][1] + bi0),
                      packbf(acc[mi][2*nfp+1][2] + bi1, acc[mi][2*nfp+1][3] + bi1));
            }
        }
        __syncthreads();

        #pragma unroll
        for (int i = tid; i < 128 * 16; i += 512) {
            const int row = i >> 4, q8 = (i & 15) * 8;
            uint4 v = *reinterpret_cast<const uint4*>(&Os[row * 136 + q8]);
            __nv_bfloat16* dst = (row < 64) ? (kb + (size_t)row * NSP)
                                            : (vb + (size_t)(row - 64) * NSP);
            *reinterpret_cast<uint4*>(&dst[n0 + q8]) = v;
        }
        __syncthreads();
    }
}

// ---------------------------------------------------------------------------
// Pass 2: per-(b,c,d) attention, 128 thr. cp.async staging, register softmax,
// O computed in two nf-halves (low reg pressure), coalesced epilogue.
// ---------------------------------------------------------------------------
__global__ void __launch_bounds__(128) attn_kernel(
    const float* __restrict__ x, float* __restrict__ out)
{
    __shared__ __align__(16) char smbuf[3 * 64 * 72 * 2];
    __nv_bfloat16* Qs = reinterpret_cast<__nv_bfloat16*>(smbuf);
    __nv_bfloat16* Ks = Qs + 64 * 72;
    __nv_bfloat16* Vs = Qs + 2 * 64 * 72;
    float* Of = reinterpret_cast<float*>(smbuf);   // 64x68 fp32, overlaps Qs+Ks

    const int tid = threadIdx.x;
    const int d = blockIdx.x, c = blockIdx.y, b = blockIdx.z;
    const size_t base = (((size_t)b * DIM + c) * DD + d) * HW;

    const char* qg = reinterpret_cast<const char*>(g_q + base);
    const char* kg = reinterpret_cast<const char*>(g_k + base);
    const char* vg = reinterpret_cast<const char*>(g_v + base);
    const uint32_t qS = smaddr(Qs), kS = smaddr(Ks), vS = smaddr(Vs);

    #pragma unroll
    for (int i = tid; i < 512; i += 128) {
        const int h = i >> 3, w8 = (i & 7) * 8;
        const uint32_t soff = (uint32_t)(h * 72 + w8) * 2;
        const int goff = i * 16;
        cpasync16(qS + soff, qg + goff);
        cpasync16(kS + soff, kg + goff);
        cpasync16(vS + soff, vg + goff);
    }
    asm volatile("cp.async.commit_group;\n");
    asm volatile("cp.async.wait_group 0;\n");
    __syncthreads();

    const int warp = tid >> 5, lane = tid & 31;
    const int lr = lane >> 2, lc = lane & 3;
    const int m = warp * 16 + lr;
    const int l8  = lane & 7;
    const int lB1 = (lane >> 3) & 1;
    const int lB2 = (lane >> 4) & 1;

    const uint32_t qBase = qS + ((warp * 16 + lB1 * 8 + l8) * 72 + lB2 * 8) * 2;
    const uint32_t kBase = kS + ((lB2 * 8 + l8) * 72 + lB1 * 8) * 2;
    const uint32_t vBase = vS + ((lB1 * 8 + l8) * 72 + lB2 * 8) * 2;

    // ---- S = Q K^T ----
    float sacc[8][4];
    #pragma unroll
    for (int nf = 0; nf < 8; ++nf)
        #pragma unroll
        for (int e = 0; e < 4; ++e) sacc[nf][e] = 0.f;

    #pragma unroll
    for (int kc = 0; kc < 4; ++kc) {
        uint32_t a[4];
        ldsm4(a[0], a[1], a[2], a[3], qBase + kc * 32);
        #pragma unroll
        for (int nfp = 0; nfp < 4; ++nfp) {
            uint32_t b0, b1, b2, b3;
            ldsm4(b0, b1, b2, b3, kBase + nfp * 2304 + kc * 32);
            mma16816(sacc[2 * nfp],     a, b0, b1);
            mma16816(sacc[2 * nfp + 1], a, b2, b3);
        }
    }

    // ---- register softmax ----
    const float sc = 0.125f;
    float mx0 = -1e30f, mx1 = -1e30f;
    #pragma unroll
    for (int nf = 0; nf < 8; ++nf) {
        mx0 = fmaxf(mx0, fmaxf(sacc[nf][0], sacc[nf][1]));
        mx1 = fmaxf(mx1, fmaxf(sacc[nf][2], sacc[nf][3]));
    }
    mx0 = fmaxf(mx0, __shfl_xor_sync(0xffffffffu, mx0, 1));
    mx0 = fmaxf(mx0, __shfl_xor_sync(0xffffffffu, mx0, 2));
    mx1 = fmaxf(mx1, __shfl_xor_sync(0xffffffffu, mx1, 1));
    mx1 = fmaxf(mx1, __shfl_xor_sync(0xffffffffu, mx1, 2));

    float sum0 = 0.f, sum1 = 0.f;
    #pragma unroll
    for (int nf = 0; nf < 8; ++nf) {
        sacc[nf][0] = __expf(sc * (sacc[nf][0] - mx0));
        sacc[nf][1] = __expf(sc * (sacc[nf][1] - mx0));
        sacc[nf][2] = __expf(sc * (sacc[nf][2] - mx1));
        sacc[nf][3] = __expf(sc * (sacc[nf][3] - mx1));
        sum0 += sacc[nf][0] + sacc[nf][1];
        sum1 += sacc[nf][2] + sacc[nf][3];
    }
    sum0 += __shfl_xor_sync(0xffffffffu, sum0, 1);
    sum0 += __shfl_xor_sync(0xffffffffu, sum0, 2);
    sum1 += __shfl_xor_sync(0xffffffffu, sum1, 1);
    sum1 += __shfl_xor_sync(0xffffffffu, sum1, 2);
    const float inv0 = 1.0f / sum0, inv1 = 1.0f / sum1;

    // ---- P fragments from S accumulators (sacc dies here) ----
    uint32_t pf[4][4];
    #pragma unroll
    for (int kc = 0; kc < 4; ++kc) {
        pf[kc][0] = packbf(sacc[2*kc][0] * inv0,   sacc[2*kc][1] * inv0);
        pf[kc][1] = packbf(sacc[2*kc][2] * inv1,   sacc[2*kc][3] * inv1);
        pf[kc][2] = packbf(sacc[2*kc+1][0] * inv0, sacc[2*kc+1][1] * inv0);
        pf[kc][3] = packbf(sacc[2*kc+1][2] * inv1, sacc[2*kc+1][3] * inv1);
    }

    // all warps done reading Qs/Ks (S-mma complete) before Of writes
    __syncthreads();

    // ---- O = P V in two nf-halves (oacc only 16 regs live) ----
    #pragma unroll
    for (int half = 0; half < 2; ++half) {
        float oacc[4][4];
        #pragma unroll
        for (int f = 0; f < 4; ++f)
            #pragma unroll
            for (int e = 0; e < 4; ++e) oacc[f][e] = 0.f;

        #pragma unroll
        for (int kc = 0; kc < 4; ++kc) {
            #pragma unroll
            for (int p = 0; p < 2; ++p) {
                const int nfp = half * 2 + p;
                uint32_t b0, b1, b2, b3;
                ldsm4t(b0, b1, b2, b3, vBase + kc * 2304 + nfp * 32);
                mma16816(oacc[2 * p],     pf[kc], b0, b1);
                mma16816(oacc[2 * p + 1], pf[kc], b2, b3);
            }
        }
        #pragma unroll
        for (int f = 0; f < 4; ++f) {
            const int n = (half * 4 + f) * 8 + lc * 2;
            *reinterpret_cast<float2*>(&Of[m * 68 + n]) =
                make_float2(oacc[f][0], oacc[f][1]);
            *reinterpret_cast<float2*>(&Of[(m + 8) * 68 + n]) =
                make_float2(oacc[f][2], oacc[f][3]);
        }
    }
    __syncthreads();

    // ---- coalesced residual + store ----
    const float* xb = x + base;
    float* ob = out + base;
    #pragma unroll
    for (int i = tid; i < 64 * 16; i += 128) {
        const int row = i >> 4, q4 = (i & 15) * 4;
        float4 o = *reinterpret_cast<const float4*>(&Of[row * 68 + q4]);
        float4 xr = *reinterpret_cast<const float4*>(&xb[row * 64 + q4]);
        o.x += xr.x; o.y += xr.y; o.z += xr.z; o.w += xr.w;
        *reinterpret_cast<float4*>(&ob[row * 64 + q4]) = o;
    }
}

// ---------------------------------------------------------------------------
extern "C" void kernel_launch(void* const* d_in, const int* in_sizes, int n_in,
                              void* d_out, int out_size)
{
    const float* x   = (const float*)d_in[0];
    const float* ctx = (const float*)d_in[1];
    const float* wq  = (const float*)d_in[2];
    const float* bq  = (const float*)d_in[3];
    const float* wk  = (const float*)d_in[4];
    const float* bk  = (const float*)d_in[5];
    const float* wv  = (const float*)d_in[6];
    const float* bv  = (const float*)d_in[7];
    float* out = (float*)d_out;

    conv_q_kernel<<<dim3(NSP / (QT * 128), BB), 256>>>(x, wq, bq);

    cudaFuncSetAttribute(conv_kv_kernel,
                         cudaFuncAttributeMaxDynamicSharedMemorySize,
                         KV_SMEM_BYTES);
    conv_kv_kernel<<<dim3(NSP / (KVT * 128), BB), 512, KV_SMEM_BYTES>>>(
        ctx, wk, bk, wv, bv);

    attn_kernel<<<dim3(DD, DIM, BB), 128>>>(x, out);
}